// round 12
// baseline (speedup 1.0000x reference)
#include <cuda_runtime.h>
#include <cuda_fp16.h>
#include <math.h>
#include <stdint.h>

#define NT    512
#define RB    128
#define AST   264            // A tile k-stride (fp16): 256 + 8 pad
#define RSTR  193

// ---- smem layout (bytes) ----
#define OFF_A       0                   // 128*264*2 = 67584 fp16
#define OFF_A0      67584               // 128*40*2 = 10240
// raw buffer (epilogue2): 128*193*4 = 98816 at sm[0], overlaps A+A0 (dead then)
#define OFF_B1S     98816               // 256 f32
#define OFF_BOS     99840               // 192 f32
#define OFF_B0S     100608              // 256 f32
#define SMEM_BYTES  101632

// ---- fragment-ordered weight images (one 512B block per (k16, nw, ntp)) ----
// g_w1f: GEMM1, 16 k16-steps x (4 nw x 4 ntp) blocks       = 256 blocks
// g_wof: GEMM2, 16 k16-steps x (4 nw x 3 ntp) blocks       = 192 blocks
// g_w0f: GEMM0,  2 k16-steps x (4 nw x 4 ntp) blocks       =  32 blocks
__device__ __align__(16) uint4 g_w1f[256 * 32];
__device__ __align__(16) uint4 g_wof[192 * 32];
__device__ __align__(16) uint4 g_w0f[32 * 32];

// ---- helpers ----
__device__ __forceinline__ uint32_t smem_u32(const void* p) {
    uint32_t a;
    asm("{ .reg .u64 t; cvta.to.shared.u64 t, %1; cvt.u32.u64 %0, t; }" : "=r"(a) : "l"(p));
    return a;
}
__device__ __forceinline__ void mma16(float* d, uint32_t a0, uint32_t a1, uint32_t a2, uint32_t a3,
                                      uint32_t b0, uint32_t b1) {
    asm volatile("mma.sync.aligned.m16n8k16.row.col.f32.f16.f16.f32 "
                 "{%0,%1,%2,%3}, {%4,%5,%6,%7}, {%8,%9}, {%0,%1,%2,%3};"
                 : "+f"(d[0]), "+f"(d[1]), "+f"(d[2]), "+f"(d[3])
                 : "r"(a0), "r"(a1), "r"(a2), "r"(a3), "r"(b0), "r"(b1));
}
__device__ __forceinline__ void ldsm4(uint32_t& r0, uint32_t& r1, uint32_t& r2, uint32_t& r3,
                                      uint32_t addr) {
    asm volatile("ldmatrix.sync.aligned.m8n8.x4.shared.b16 {%0,%1,%2,%3}, [%4];"
                 : "=r"(r0), "=r"(r1), "=r"(r2), "=r"(r3) : "r"(addr));
}

// ---- fast transcendentals (MUFU-based; error << 1e-4 budget) ----
__device__ __forceinline__ float flog1p(float x) {       // x >= 0
    return (x < 1e-2f) ? x * (1.0f - 0.5f * x) : __logf(1.0f + x);
}
__device__ __forceinline__ float softplusf(float v) {
    return fmaxf(v, 0.0f) + flog1p(__expf(-fabsf(v)));
}

// K=32 panel: A frags via ldmatrix (smem), B frags via one LDG.128 per (ks,ntp).
// w is pre-offset by (nw, lane); block element index = (ks*KBLKS + ntp)*32.
template<int NTILES, int ASTRIDE, int KBLKS>
__device__ __forceinline__ void panel_ldg(uint32_t aLane, const uint4* __restrict__ w,
                                          float d[2][8][4])
{
    #pragma unroll
    for (int ks = 0; ks < 2; ks++) {
        uint32_t a[2][4];
        #pragma unroll
        for (int mt = 0; mt < 2; mt++)
            ldsm4(a[mt][0], a[mt][1], a[mt][2], a[mt][3],
                  aLane + ks * 32 + mt * (16 * ASTRIDE * 2));
        #pragma unroll
        for (int ntp = 0; ntp < NTILES / 2; ntp++) {
            const uint4 b = w[(ks * KBLKS + ntp) * 32];
            #pragma unroll
            for (int mt = 0; mt < 2; mt++) {
                mma16(d[mt][2 * ntp],     a[mt][0], a[mt][1], a[mt][2], a[mt][3], b.x, b.y);
                mma16(d[mt][2 * ntp + 1], a[mt][0], a[mt][1], a[mt][2], a[mt][3], b.z, b.w);
            }
        }
    }
}

// ---- prep kernels: build fragment-ordered weight blocks ----
__device__ __forceinline__ uint32_t pack_h2(float lo, float hi) {
    __half2 h = __floats2half2_rn(lo, hi);
    return *(uint32_t*)&h;
}

__global__ void prep_w1f(const float* __restrict__ W1) {
    int idx = blockIdx.x * blockDim.x + threadIdx.x;      // 8192
    int blk = idx >> 5, lane = idx & 31;
    int pks = blk >> 4, rem = blk & 15;
    int nw = rem >> 2, ntp = rem & 3;
    int qr = lane >> 2, tc = lane & 3;
    int n0 = nw * 64 + ntp * 16;
    int kb = pks * 16 + 2 * tc;
    uint4 v;
    v.x = pack_h2(W1[kb * 256 + n0 + qr],        W1[(kb + 1) * 256 + n0 + qr]);
    v.y = pack_h2(W1[(kb + 8) * 256 + n0 + qr],  W1[(kb + 9) * 256 + n0 + qr]);
    v.z = pack_h2(W1[kb * 256 + n0 + 8 + qr],       W1[(kb + 1) * 256 + n0 + 8 + qr]);
    v.w = pack_h2(W1[(kb + 8) * 256 + n0 + 8 + qr], W1[(kb + 9) * 256 + n0 + 8 + qr]);
    g_w1f[blk * 32 + lane] = v;
}

__global__ void prep_wof(const float* __restrict__ Wout) {
    int idx = blockIdx.x * blockDim.x + threadIdx.x;      // 6144
    int blk = idx >> 5, lane = idx & 31;
    int pks = blk / 12, rem = blk % 12;
    int nw = rem / 3, ntp = rem % 3;
    int qr = lane >> 2, tc = lane & 3;
    int n0 = nw * 48 + ntp * 16;
    int kb = pks * 16 + 2 * tc;
    int na = n0 + qr, nb = n0 + 8 + qr;
    float a0 = (na < 184) ? Wout[kb * 184 + na] : 0.0f;
    float a1 = (na < 184) ? Wout[(kb + 1) * 184 + na] : 0.0f;
    float a2 = (na < 184) ? Wout[(kb + 8) * 184 + na] : 0.0f;
    float a3 = (na < 184) ? Wout[(kb + 9) * 184 + na] : 0.0f;
    float c0 = (nb < 184) ? Wout[kb * 184 + nb] : 0.0f;
    float c1 = (nb < 184) ? Wout[(kb + 1) * 184 + nb] : 0.0f;
    float c2 = (nb < 184) ? Wout[(kb + 8) * 184 + nb] : 0.0f;
    float c3 = (nb < 184) ? Wout[(kb + 9) * 184 + nb] : 0.0f;
    uint4 v;
    v.x = pack_h2(a0, a1);
    v.y = pack_h2(a2, a3);
    v.z = pack_h2(c0, c1);
    v.w = pack_h2(c2, c3);
    g_wof[blk * 32 + lane] = v;
}

// W0 3-term layout along k: k0..7 W0hi (vs x2hi), k8..15 W0hi (vs x2lo), k16..23 W0lo, k24..31 zero
__device__ __forceinline__ float w0_elem(const float* W0, int kk, int n) {
    if (kk < 16) return __half2float(__float2half_rn(W0[(kk & 7) * 256 + n]));
    if (kk < 24) {
        float w = W0[(kk - 16) * 256 + n];
        return w - __half2float(__float2half_rn(w));   // rounded again on pack; lo fits fp16
    }
    return 0.0f;
}
__global__ void prep_w0f(const float* __restrict__ W0) {
    int idx = blockIdx.x * blockDim.x + threadIdx.x;      // 1024
    int blk = idx >> 5, lane = idx & 31;
    int ks = blk >> 4, rem = blk & 15;
    int nw = rem >> 2, ntp = rem & 3;
    int qr = lane >> 2, tc = lane & 3;
    int n0 = nw * 64 + ntp * 16;
    int kb = ks * 16 + 2 * tc;
    uint4 v;
    v.x = pack_h2(w0_elem(W0, kb, n0 + qr),     w0_elem(W0, kb + 1, n0 + qr));
    v.y = pack_h2(w0_elem(W0, kb + 8, n0 + qr), w0_elem(W0, kb + 9, n0 + qr));
    v.z = pack_h2(w0_elem(W0, kb, n0 + 8 + qr),     w0_elem(W0, kb + 1, n0 + 8 + qr));
    v.w = pack_h2(w0_elem(W0, kb + 8, n0 + 8 + qr), w0_elem(W0, kb + 9, n0 + 8 + qr));
    g_w0f[blk * 32 + lane] = v;
}

// ---- main kernel ----
__global__ void __launch_bounds__(NT, 1)
coupling_hmma_kernel(const float* __restrict__ x,
                     const float* __restrict__ b0,
                     const float* __restrict__ b1,
                     const float* __restrict__ bout,
                     float* __restrict__ out,
                     int B)
{
    extern __shared__ char sm[];
    const int tid = threadIdx.x;
    const int wid = tid >> 5, lane = tid & 31;
    const int mw = wid & 3, nw = wid >> 2;          // 4 m-warps x 4 n-warps
    const int qr = lane >> 2, qc = (lane & 3) * 2;
    const int row0 = blockIdx.x * RB;
    const uint32_t sm_u32 = smem_u32(sm);

    float* b0s = (float*)(sm + OFF_B0S);
    float* b1s = (float*)(sm + OFF_B1S);
    float* bos = (float*)(sm + OFF_BOS);

    // per-lane ldmatrix A address components
    const int aRow = (lane & 15);
    const int aKof = (lane >> 4) * 8;
    const uint32_t aLaneA = sm_u32 + OFF_A + (((mw * 32 + aRow) * AST) + aKof) * 2;
    const uint32_t aLane0 = sm_u32 + OFF_A0 + (((mw * 32 + aRow) * 40) + aKof) * 2;

    // per-warp fragment-block pointers (pre-offset by nw and lane)
    const uint4* __restrict__ w1p = g_w1f + (size_t)nw * 4 * 32 + lane;
    const uint4* __restrict__ wop = g_wof + (size_t)nw * 3 * 32 + lane;
    const uint4* __restrict__ w0p = g_w0f + (size_t)nw * 4 * 32 + lane;

    // ---- consts + A0 staging (exact hi/lo split of x2) ----
    for (int i = tid; i < 256; i += NT) { b0s[i] = b0[i]; b1s[i] = b1[i]; }
    for (int i = tid; i < 192; i += NT) bos[i] = (i < 184) ? bout[i] : 0.0f;
    if (tid < RB) {
        const float4* xp = (const float4*)(x + (size_t)(row0 + tid) * 16);
        float4 xc = xp[2], xd = xp[3];
        float xv[8] = {xc.x, xc.y, xc.z, xc.w, xd.x, xd.y, xd.z, xd.w};
        __half2* a0 = (__half2*)(sm + OFF_A0 + tid * 40 * 2);
        #pragma unroll
        for (int j = 0; j < 8; j += 2) {
            __half h0 = __float2half_rn(xv[j]);
            __half h1 = __float2half_rn(xv[j + 1]);
            __half l0 = __float2half_rn(xv[j] - __half2float(h0));
            __half l1 = __float2half_rn(xv[j + 1] - __half2float(h1));
            a0[j / 2]      = __half2(h0, h1);   // k 0..7  : x2hi
            a0[4 + j / 2]  = __half2(l0, l1);   // k 8..15 : x2lo
            a0[8 + j / 2]  = __half2(h0, h1);   // k 16..23: x2hi (vs W0lo)
            a0[12 + j / 2] = __half2(__float2half_rn(0.f), __float2half_rn(0.f));
            a0[16 + j / 2] = __half2(__float2half_rn(0.f), __float2half_rn(0.f));
        }
    }
    __syncthreads();

    float d[2][8][4];
    #pragma unroll
    for (int mt = 0; mt < 2; mt++)
        #pragma unroll
        for (int nt = 0; nt < 8; nt++)
            #pragma unroll
            for (int i = 0; i < 4; i++) d[mt][nt][i] = 0.0f;

    // ---- GEMM0 (K=32, exact 3-term hi/lo; W frags via LDG) ----
    panel_ldg<8, 40, 16>(aLane0, w0p, d);

    // ---- epilogue0: h0 = relu(d + b0) -> fp16 A tile (disjoint from A0) ----
    #pragma unroll
    for (int mt = 0; mt < 2; mt++) {
        const int r0 = mw * 32 + mt * 16 + qr;
        #pragma unroll
        for (int nt = 0; nt < 8; nt++) {
            const int c = nw * 64 + nt * 8 + qc;
            const float g0 = b0s[c], g1 = b0s[c + 1];
            float v00 = fmaxf(d[mt][nt][0] + g0, 0.f);
            float v01 = fmaxf(d[mt][nt][1] + g1, 0.f);
            float v10 = fmaxf(d[mt][nt][2] + g0, 0.f);
            float v11 = fmaxf(d[mt][nt][3] + g1, 0.f);
            *(__half2*)(sm + OFF_A + ((size_t)r0 * AST + c) * 2) = __floats2half2_rn(v00, v01);
            *(__half2*)(sm + OFF_A + ((size_t)(r0 + 8) * AST + c) * 2) = __floats2half2_rn(v10, v11);
            #pragma unroll
            for (int i = 0; i < 4; i++) d[mt][nt][i] = 0.0f;
        }
    }
    __syncthreads();

    // ---- GEMM1: 8 K=32 panels, no barriers ----
    #pragma unroll 2
    for (int p = 0; p < 8; p++)
        panel_ldg<8, AST, 16>(aLaneA + p * 64, w1p + (size_t)p * 2 * 16 * 32, d);

    __syncthreads();   // all GEMM1 A reads done

    // ---- epilogue1: h1 = relu(d + b1) -> fp16 A tile ----
    #pragma unroll
    for (int mt = 0; mt < 2; mt++) {
        const int r0 = mw * 32 + mt * 16 + qr;
        #pragma unroll
        for (int nt = 0; nt < 8; nt++) {
            const int c = nw * 64 + nt * 8 + qc;
            const float g0 = b1s[c], g1 = b1s[c + 1];
            float v00 = fmaxf(d[mt][nt][0] + g0, 0.f);
            float v01 = fmaxf(d[mt][nt][1] + g1, 0.f);
            float v10 = fmaxf(d[mt][nt][2] + g0, 0.f);
            float v11 = fmaxf(d[mt][nt][3] + g1, 0.f);
            *(__half2*)(sm + OFF_A + ((size_t)r0 * AST + c) * 2) = __floats2half2_rn(v00, v01);
            *(__half2*)(sm + OFF_A + ((size_t)(r0 + 8) * AST + c) * 2) = __floats2half2_rn(v10, v11);
            #pragma unroll
            for (int i = 0; i < 4; i++) d[mt][nt][i] = 0.0f;
        }
    }
    __syncthreads();

    // ---- GEMM2: 8 K=32 panels, no barriers ----
    #pragma unroll 2
    for (int p = 0; p < 8; p++)
        panel_ldg<6, AST, 12>(aLaneA + p * 64, wop + (size_t)p * 2 * 12 * 32, d);

    __syncthreads();   // all GEMM2 A reads done

    // ---- epilogue2: raw = d + bout -> smem f32 [128][193] (overlaps A+A0) ----
    float* rawS = (float*)sm;
    #pragma unroll
    for (int mt = 0; mt < 2; mt++) {
        const int r0 = mw * 32 + mt * 16 + qr;
        #pragma unroll
        for (int nt = 0; nt < 6; nt++) {
            const int c = nw * 48 + nt * 8 + qc;
            rawS[r0 * RSTR + c]           = d[mt][nt][0] + bos[c];
            rawS[r0 * RSTR + c + 1]       = d[mt][nt][1] + bos[c + 1];
            rawS[(r0 + 8) * RSTR + c]     = d[mt][nt][2] + bos[c];
            rawS[(r0 + 8) * RSTR + c + 1] = d[mt][nt][3] + bos[c + 1];
        }
    }
    __syncthreads();

    // ---- spline: 4 threads/row, 2 transforms each (fast-math MUFU path) ----
    {
        const int r = tid >> 2;
        const int q = tid & 3;
        const int ts = q * 2;
        const size_t grow = (size_t)(row0 + r) * 16;
        const float2 x1p = *(const float2*)(x + grow + ts);
        const float x1v[2] = {x1p.x, x1p.y};
        const float CNST = logf(expf(1.0f - 1e-4f) - 1.0f);
        float yv[2];
        float ldsum = 0.0f;

        #pragma unroll
        for (int tt = 0; tt < 2; tt++) {
            const float* raw = rawS + r * RSTR + (ts + tt) * 23;
            const float xv = x1v[tt];

            float rw[8], rh[8];
            #pragma unroll
            for (int c = 0; c < 8; c++) { rw[c] = raw[c]; rh[c] = raw[8 + c]; }

            float m = rw[0];
            #pragma unroll
            for (int c = 1; c < 8; c++) m = fmaxf(m, rw[c]);
            float sum = 0.0f, ew[8];
            #pragma unroll
            for (int c = 0; c < 8; c++) { ew[c] = __expf(rw[c] - m); sum += ew[c]; }
            float inv = __fdividef(1.0f, sum);
            float wdt[8];
            #pragma unroll
            for (int c = 0; c < 8; c++) wdt[c] = 2.0f * (1e-4f + (1.0f - 8e-4f) * ew[c] * inv);

            m = rh[0];
            #pragma unroll
            for (int c = 1; c < 8; c++) m = fmaxf(m, rh[c]);
            sum = 0.0f;
            #pragma unroll
            for (int c = 0; c < 8; c++) { ew[c] = __expf(rh[c] - m); sum += ew[c]; }
            inv = __fdividef(1.0f, sum);
            float hgt[8];
            #pragma unroll
            for (int c = 0; c < 8; c++) hgt[c] = 2.0f * (1e-4f + (1.0f - 8e-4f) * ew[c] * inv);

            float dv[9];
            dv[0] = 1.0f; dv[8] = 1.0f;
            #pragma unroll
            for (int c = 0; c < 7; c++) dv[c + 1] = softplusf(raw[16 + c] + CNST) + 1e-4f;

            const bool mask = (xv <= -0.999f) || (xv >= 0.999f);
            const float xin = mask ? 0.0f : xv;

            float cx = -1.0f, cy = -1.0f;
            float xk = -1.0f, yk = -1.0f, wk = wdt[0], hk = hgt[0], dk = dv[0], dk1 = dv[1];
            #pragma unroll
            for (int i = 0; i < 8; i++) {
                if (cx <= xin) { xk = cx; yk = cy; wk = wdt[i]; hk = hgt[i]; dk = dv[i]; dk1 = dv[i + 1]; }
                cx += wdt[i]; cy += hgt[i];
            }

            const float invwk = __fdividef(1.0f, wk);
            const float sk   = hk * invwk;
            const float eps  = (xin - xk) * invwk;
            const float et   = eps * (1.0f - eps);
            const float e2   = eps * eps;
            const float beta = sk + (dk1 + dk - 2.0f * sk) * et;
            const float alp  = hk * (sk * e2 + dk * et);
            yv[tt] = mask ? xv : (yk + __fdividef(alp, beta));
            const float ome = 1.0f - eps;
            float ld = 2.0f * __logf(sk)
                     + __logf(dk1 * e2 + 2.0f * sk * et + dk * ome * ome)
                     - 2.0f * __logf(beta);
            ldsum += mask ? 0.0f : ld;
        }

        // outputs
        *(float2*)(out + grow + ts) = make_float2(yv[0], yv[1]);
        if (q < 2)
            *(float4*)(out + grow + 8 + q * 4) = *(const float4*)(x + grow + 8 + q * 4);

        ldsum += __shfl_xor_sync(0xffffffffu, ldsum, 1);
        ldsum += __shfl_xor_sync(0xffffffffu, ldsum, 2);
        if (q == 0)
            out[(size_t)B * 16 + row0 + r] = ldsum;
    }
}

extern "C" void kernel_launch(void* const* d_in, const int* in_sizes, int n_in,
                              void* d_out, int out_size) {
    const float* x    = (const float*)d_in[0];
    const float* W0   = (const float*)d_in[1];
    const float* b0   = (const float*)d_in[2];
    const float* W1   = (const float*)d_in[3];
    const float* b1   = (const float*)d_in[4];
    const float* Wout = (const float*)d_in[5];
    const float* bout = (const float*)d_in[6];
    float* out = (float*)d_out;

    const int B = in_sizes[0] / 16;

    prep_w1f<<<32, 256>>>(W1);
    prep_wof<<<24, 256>>>(Wout);
    prep_w0f<<<4, 256>>>(W0);

    cudaFuncSetAttribute(coupling_hmma_kernel,
                         cudaFuncAttributeMaxDynamicSharedMemorySize, SMEM_BYTES);
    coupling_hmma_kernel<<<B / RB, NT, SMEM_BYTES>>>(x, b0, b1, bout, out, B);
}

// round 13
// speedup vs baseline: 1.3766x; 1.3766x over previous
#include <cuda_runtime.h>
#include <cuda_fp16.h>
#include <math.h>
#include <stdint.h>

#define NT    512
#define RB    128
#define AST   264            // A tile k-stride (fp16): 256 + 8 pad
#define WST   40             // W panel k-stride (fp16): 32 + 8 pad
#define RSTR  193

// ---- smem layout (bytes) ----
#define OFF_A       0                   // 128*264*2 = 67584 fp16
#define OFF_WP      67584               // 3 stage slots * 40960
#define SLOT_B      40960               // one stage = 2 K=32 panels
#define OFF_A0      149504              // inside slot 2: 128*40*2 = 10240
#define OFF_W0P     159744              // inside slot 2: 256*40*2 = 20480
#define OFF_B1S     190464              // 256 f32
#define OFF_BOS     191488              // 192 f32
#define OFF_B0S     192256              // 256 f32
#define OFF_X1S     193280              // 128*8 f32 = 4096
#define OFF_X2S     197376              // 128*8 f32 = 4096
#define SMEM_BYTES  201472
// raw buffer (epilogue2): 128*193*4 = 98816 at sm[0], overlaps A+slot0 (dead then)

#define PAN1_B 20480                    // 256*40*2 (one K=32 GEMM1 panel)
#define PAN2_B 15360                    // 192*40*2
#define STG1_B 40960                    // GEMM1 stage (2 panels)
#define STG2_B 30720                    // GEMM2 stage (2 panels)

// ---- prebuilt fp16 weight panels ----
__device__ __align__(16) __half g_w1[8 * 256 * 40];
__device__ __align__(16) __half g_wo[8 * 192 * 40];
__device__ __align__(16) __half g_w0[256 * 40];     // [W0hi | W0hi | W0lo | 0] k-layout

// ---- helpers ----
__device__ __forceinline__ uint32_t smem_u32(const void* p) {
    uint32_t a;
    asm("{ .reg .u64 t; cvta.to.shared.u64 t, %1; cvt.u32.u64 %0, t; }" : "=r"(a) : "l"(p));
    return a;
}
__device__ __forceinline__ void cp16(uint32_t dst, const void* src) {
    asm volatile("cp.async.cg.shared.global [%0], [%1], 16;" :: "r"(dst), "l"(src));
}
#define CP_COMMIT() asm volatile("cp.async.commit_group;")
#define CP_WAIT0()  asm volatile("cp.async.wait_group 0;")
#define CP_WAIT1()  asm volatile("cp.async.wait_group 1;")

__device__ __forceinline__ void mma16(float* d, uint32_t a0, uint32_t a1, uint32_t a2, uint32_t a3,
                                      uint32_t b0, uint32_t b1) {
    asm volatile("mma.sync.aligned.m16n8k16.row.col.f32.f16.f16.f32 "
                 "{%0,%1,%2,%3}, {%4,%5,%6,%7}, {%8,%9}, {%0,%1,%2,%3};"
                 : "+f"(d[0]), "+f"(d[1]), "+f"(d[2]), "+f"(d[3])
                 : "r"(a0), "r"(a1), "r"(a2), "r"(a3), "r"(b0), "r"(b1));
}
__device__ __forceinline__ void ldsm4(uint32_t& r0, uint32_t& r1, uint32_t& r2, uint32_t& r3,
                                      uint32_t addr) {
    asm volatile("ldmatrix.sync.aligned.m8n8.x4.shared.b16 {%0,%1,%2,%3}, [%4];"
                 : "=r"(r0), "=r"(r1), "=r"(r2), "=r"(r3) : "r"(addr));
}

// ---- fast transcendentals (MUFU-based; error << 1e-4 budget) ----
__device__ __forceinline__ float flog1p(float x) {       // x >= 0
    return (x < 1e-2f) ? x * (1.0f - 0.5f * x) : __logf(1.0f + x);
}
__device__ __forceinline__ float softplusf(float v) {
    return fmaxf(v, 0.0f) + flog1p(__expf(-fabsf(v)));
}

// k-panel compute (K=32) via ldmatrix; 2 m-tiles (32-row warp tile)
template<int NTILES, int ASTRIDE>
__device__ __forceinline__ void panel_compute(uint32_t aLane, uint32_t wLane, float d[2][8][4])
{
    #pragma unroll
    for (int ks = 0; ks < 2; ks++) {
        const uint32_t aK = aLane + ks * 32;      // +16 halves
        const uint32_t wK = wLane + ks * 32;
        uint32_t a[2][4];
        #pragma unroll
        for (int mt = 0; mt < 2; mt++)
            ldsm4(a[mt][0], a[mt][1], a[mt][2], a[mt][3], aK + mt * (16 * ASTRIDE * 2));
        #pragma unroll
        for (int ntp = 0; ntp < NTILES / 2; ntp++) {
            uint32_t b0, b1, b2, b3;
            ldsm4(b0, b1, b2, b3, wK + ntp * (16 * WST * 2));
            #pragma unroll
            for (int mt = 0; mt < 2; mt++) {
                mma16(d[mt][2 * ntp],     a[mt][0], a[mt][1], a[mt][2], a[mt][3], b0, b1);
                mma16(d[mt][2 * ntp + 1], a[mt][0], a[mt][1], a[mt][2], a[mt][3], b2, b3);
            }
        }
    }
}

// ---- prep kernels ----
__global__ void prep_w1(const float* __restrict__ W1) {
    int idx = blockIdx.x * blockDim.x + threadIdx.x;      // 81920
    int p = idx / 10240, rem = idx % 10240;
    int n = rem / 40, kk = rem % 40;
    float w = (kk < 32) ? W1[(p * 32 + kk) * 256 + n] : 0.0f;
    g_w1[idx] = __float2half_rn(w);
}
__global__ void prep_wo(const float* __restrict__ Wout) {
    int idx = blockIdx.x * blockDim.x + threadIdx.x;      // 61440
    int p = idx / 7680, rem = idx % 7680;
    int n = rem / 40, kk = rem % 40;
    float w = (kk < 32 && n < 184) ? Wout[(p * 32 + kk) * 184 + n] : 0.0f;
    g_wo[idx] = __float2half_rn(w);
}
__global__ void prep_w0(const float* __restrict__ W0) {
    int idx = blockIdx.x * blockDim.x + threadIdx.x;      // 10240
    int n = idx / 40, kk = idx % 40;
    __half v = __float2half_rn(0.0f);
    if (kk < 16) {                       // W0hi (k 0..7 for x2hi, 8..15 for x2lo)
        float w = W0[(kk & 7) * 256 + n];
        v = __float2half_rn(w);
    } else if (kk < 24) {                // W0lo (k 16..23 vs x2hi)
        float w = W0[(kk - 16) * 256 + n];
        __half h = __float2half_rn(w);
        v = __float2half_rn(w - __half2float(h));
    }
    g_w0[idx] = v;
}

// ---- main kernel ----
__global__ void __launch_bounds__(NT, 1)
coupling_hmma_kernel(const float* __restrict__ x,
                     const float* __restrict__ b0,
                     const float* __restrict__ b1,
                     const float* __restrict__ bout,
                     float* __restrict__ out,
                     int B)
{
    extern __shared__ char sm[];
    const int tid = threadIdx.x;
    const int wid = tid >> 5, lane = tid & 31;
    const int mw = wid & 3, nw = wid >> 2;          // 4 m-warps x 4 n-warps
    const int qr = lane >> 2, qc = (lane & 3) * 2;
    const int row0 = blockIdx.x * RB;
    const uint32_t sm_u32 = smem_u32(sm);
    const uint32_t wp_u32 = sm_u32 + OFF_WP;

    float* b0s = (float*)(sm + OFF_B0S);
    float* b1s = (float*)(sm + OFF_B1S);
    float* bos = (float*)(sm + OFF_BOS);
    float* x1s = (float*)(sm + OFF_X1S);
    float* x2s = (float*)(sm + OFF_X2S);

    // per-lane ldmatrix address components
    const int aRow = (lane & 15);
    const int aKof = (lane >> 4) * 8;
    const int wRow = (lane & 7) + ((lane >> 4) * 8);
    const int wKof = ((lane >> 3) & 1) * 8;
    const uint32_t aLaneA = sm_u32 + OFF_A + (((mw * 32 + aRow) * AST) + aKof) * 2;
    const uint32_t wRel1 = (((nw * 64 + wRow) * WST) + wKof) * 2;   // GEMM1: nbase = nw*64
    const uint32_t wRel2 = (((nw * 48 + wRow) * WST) + wKof) * 2;   // GEMM2: nbase = nw*48

    // ---- prefetch: stage0 (slot0), stage1 (slot1), W0 panel (slot2) ----
    for (int i = tid; i < STG1_B / 16; i += NT)
        cp16(wp_u32 + i * 16, (const char*)g_w1 + i * 16);
    CP_COMMIT();
    for (int i = tid; i < STG1_B / 16; i += NT)
        cp16(wp_u32 + SLOT_B + i * 16, (const char*)g_w1 + STG1_B + i * 16);
    CP_COMMIT();
    {
        const uint32_t w0p = sm_u32 + OFF_W0P;
        for (int i = tid; i < 1280; i += NT)
            cp16(w0p + i * 16, (const char*)g_w0 + i * 16);
    }
    CP_COMMIT();

    // ---- consts + x staging + A0 staging (exact hi/lo split of x2) ----
    for (int i = tid; i < 256; i += NT) { b0s[i] = b0[i]; b1s[i] = b1[i]; }
    for (int i = tid; i < 192; i += NT) bos[i] = (i < 184) ? bout[i] : 0.0f;
    if (tid < RB) {
        const float4* xp = (const float4*)(x + (size_t)(row0 + tid) * 16);
        float4 xa = xp[0], xb = xp[1], xc = xp[2], xd = xp[3];
        ((float4*)x1s)[tid * 2]     = xa;
        ((float4*)x1s)[tid * 2 + 1] = xb;
        ((float4*)x2s)[tid * 2]     = xc;
        ((float4*)x2s)[tid * 2 + 1] = xd;
        float xv[8] = {xc.x, xc.y, xc.z, xc.w, xd.x, xd.y, xd.z, xd.w};
        __half2* a0 = (__half2*)(sm + OFF_A0 + tid * 40 * 2);
        #pragma unroll
        for (int j = 0; j < 8; j += 2) {
            __half h0 = __float2half_rn(xv[j]);
            __half h1 = __float2half_rn(xv[j + 1]);
            __half l0 = __float2half_rn(xv[j] - __half2float(h0));
            __half l1 = __float2half_rn(xv[j + 1] - __half2float(h1));
            a0[j / 2]      = __half2(h0, h1);   // k 0..7  : x2hi
            a0[4 + j / 2]  = __half2(l0, l1);   // k 8..15 : x2lo
            a0[8 + j / 2]  = __half2(h0, h1);   // k 16..23: x2hi (vs W0lo)
            a0[12 + j / 2] = __half2(__float2half_rn(0.f), __float2half_rn(0.f));
            a0[16 + j / 2] = __half2(__float2half_rn(0.f), __float2half_rn(0.f));
        }
    }
    CP_WAIT0();
    __syncthreads();

    float d[2][8][4];
    #pragma unroll
    for (int mt = 0; mt < 2; mt++)
        #pragma unroll
        for (int nt = 0; nt < 8; nt++)
            #pragma unroll
            for (int i = 0; i < 4; i++) d[mt][nt][i] = 0.0f;

    // ---- GEMM0 on tensor pipe (K=32, exact 3-term hi/lo) ----
    {
        const uint32_t aLane0 = sm_u32 + OFF_A0 + (((mw * 32 + aRow) * 40) + aKof) * 2;
        const uint32_t wLane0 = sm_u32 + OFF_W0P + wRel1;
        panel_compute<8, 40>(aLane0, wLane0, d);
    }

    // ---- epilogue0: h0 = relu(d + b0) -> fp16 A tile ----
    // (ordering to mainloop A reads + slot-2 reuse is provided by the s=0 loop-top sync)
    #pragma unroll
    for (int mt = 0; mt < 2; mt++) {
        const int r0 = mw * 32 + mt * 16 + qr;
        #pragma unroll
        for (int nt = 0; nt < 8; nt++) {
            const int c = nw * 64 + nt * 8 + qc;
            const float g0 = b0s[c], g1 = b0s[c + 1];
            float v00 = fmaxf(d[mt][nt][0] + g0, 0.f);
            float v01 = fmaxf(d[mt][nt][1] + g1, 0.f);
            float v10 = fmaxf(d[mt][nt][2] + g0, 0.f);
            float v11 = fmaxf(d[mt][nt][3] + g1, 0.f);
            *(__half2*)(sm + OFF_A + ((size_t)r0 * AST + c) * 2) = __floats2half2_rn(v00, v01);
            *(__half2*)(sm + OFF_A + ((size_t)(r0 + 8) * AST + c) * 2) = __floats2half2_rn(v10, v11);
            #pragma unroll
            for (int i = 0; i < 4; i++) d[mt][nt][i] = 0.0f;
        }
    }

    // ---- stage pipeline: s 0..3 = GEMM1 (panels 2s,2s+1), s 4..7 = GEMM2 ----
    for (int s = 0; s < 8; s++) {
        CP_WAIT1();
        __syncthreads();

        if (s == 4) {
            // epilogue1: h1 = relu(d + b1) -> fp16 A tile
            #pragma unroll
            for (int mt = 0; mt < 2; mt++) {
                const int r0 = mw * 32 + mt * 16 + qr;
                #pragma unroll
                for (int nt = 0; nt < 8; nt++) {
                    const int c = nw * 64 + nt * 8 + qc;
                    const float g0 = b1s[c], g1 = b1s[c + 1];
                    float v00 = fmaxf(d[mt][nt][0] + g0, 0.f);
                    float v01 = fmaxf(d[mt][nt][1] + g1, 0.f);
                    float v10 = fmaxf(d[mt][nt][2] + g0, 0.f);
                    float v11 = fmaxf(d[mt][nt][3] + g1, 0.f);
                    *(__half2*)(sm + OFF_A + ((size_t)r0 * AST + c) * 2) = __floats2half2_rn(v00, v01);
                    *(__half2*)(sm + OFF_A + ((size_t)(r0 + 8) * AST + c) * 2) = __floats2half2_rn(v10, v11);
                    #pragma unroll
                    for (int i = 0; i < 4; i++) d[mt][nt][i] = 0.0f;
                }
            }
            // A-tile rows are private to the mw-group (same 4 warps write & read)
            asm volatile("bar.sync %0, %1;" :: "r"(1 + mw), "r"(128) : "memory");
        }

        // issue stage s+2 into slot (s+2)%3 (its occupant s-1 consumed last iter)
        if (s + 2 < 8) {
            const int ns = s + 2;
            uint32_t dst = wp_u32 + (ns % 3) * SLOT_B;
            if (ns < 4) {
                const char* src = (const char*)g_w1 + (size_t)ns * STG1_B;
                for (int i = tid; i < STG1_B / 16; i += NT) cp16(dst + i * 16, src + i * 16);
            } else {
                const char* src = (const char*)g_wo + (size_t)(ns - 4) * STG2_B;
                for (int i = tid; i < STG2_B / 16; i += NT) cp16(dst + i * 16, src + i * 16);
            }
        }
        CP_COMMIT();

        const uint32_t slot = wp_u32 + (s % 3) * SLOT_B;
        if (s < 4) {
            panel_compute<8, AST>(aLaneA + (2 * s) * 64,     slot + wRel1, d);
            panel_compute<8, AST>(aLaneA + (2 * s + 1) * 64, slot + PAN1_B + wRel1, d);
        } else {
            panel_compute<6, AST>(aLaneA + (2 * s - 8) * 64, slot + wRel2, d);
            panel_compute<6, AST>(aLaneA + (2 * s - 7) * 64, slot + PAN2_B + wRel2, d);
        }
    }
    __syncthreads();   // all GEMM2 A/W reads done

    // ---- epilogue2: raw = d + bout -> smem f32 [128][193] (overlaps A+slot0) ----
    float* rawS = (float*)sm;
    #pragma unroll
    for (int mt = 0; mt < 2; mt++) {
        const int r0 = mw * 32 + mt * 16 + qr;
        #pragma unroll
        for (int nt = 0; nt < 6; nt++) {
            const int c = nw * 48 + nt * 8 + qc;
            rawS[r0 * RSTR + c]           = d[mt][nt][0] + bos[c];
            rawS[r0 * RSTR + c + 1]       = d[mt][nt][1] + bos[c + 1];
            rawS[(r0 + 8) * RSTR + c]     = d[mt][nt][2] + bos[c];
            rawS[(r0 + 8) * RSTR + c + 1] = d[mt][nt][3] + bos[c + 1];
        }
    }
    __syncthreads();

    // ---- spline: 4 threads/row, 2 transforms each (fast-math MUFU path) ----
    {
        const int r = tid >> 2;
        const int q = tid & 3;
        const int ts = q * 2;
        const size_t grow = (size_t)(row0 + r) * 16;
        const float x1v[2] = {x1s[r * 8 + ts], x1s[r * 8 + ts + 1]};
        const float CNST = logf(expf(1.0f - 1e-4f) - 1.0f);
        float yv[2];
        float ldsum = 0.0f;

        #pragma unroll
        for (int tt = 0; tt < 2; tt++) {
            const float* raw = rawS + r * RSTR + (ts + tt) * 23;
            const float xv = x1v[tt];

            float rw[8], rh[8];
            #pragma unroll
            for (int c = 0; c < 8; c++) { rw[c] = raw[c]; rh[c] = raw[8 + c]; }

            float m = rw[0];
            #pragma unroll
            for (int c = 1; c < 8; c++) m = fmaxf(m, rw[c]);
            float sum = 0.0f, ew[8];
            #pragma unroll
            for (int c = 0; c < 8; c++) { ew[c] = __expf(rw[c] - m); sum += ew[c]; }
            float inv = __fdividef(1.0f, sum);
            float wdt[8];
            #pragma unroll
            for (int c = 0; c < 8; c++) wdt[c] = 2.0f * (1e-4f + (1.0f - 8e-4f) * ew[c] * inv);

            m = rh[0];
            #pragma unroll
            for (int c = 1; c < 8; c++) m = fmaxf(m, rh[c]);
            sum = 0.0f;
            #pragma unroll
            for (int c = 0; c < 8; c++) { ew[c] = __expf(rh[c] - m); sum += ew[c]; }
            inv = __fdividef(1.0f, sum);
            float hgt[8];
            #pragma unroll
            for (int c = 0; c < 8; c++) hgt[c] = 2.0f * (1e-4f + (1.0f - 8e-4f) * ew[c] * inv);

            float dv[9];
            dv[0] = 1.0f; dv[8] = 1.0f;
            #pragma unroll
            for (int c = 0; c < 7; c++) dv[c + 1] = softplusf(raw[16 + c] + CNST) + 1e-4f;

            const bool mask = (xv <= -0.999f) || (xv >= 0.999f);
            const float xin = mask ? 0.0f : xv;

            float cx = -1.0f, cy = -1.0f;
            float xk = -1.0f, yk = -1.0f, wk = wdt[0], hk = hgt[0], dk = dv[0], dk1 = dv[1];
            #pragma unroll
            for (int i = 0; i < 8; i++) {
                if (cx <= xin) { xk = cx; yk = cy; wk = wdt[i]; hk = hgt[i]; dk = dv[i]; dk1 = dv[i + 1]; }
                cx += wdt[i]; cy += hgt[i];
            }

            const float invwk = __fdividef(1.0f, wk);
            const float sk   = hk * invwk;
            const float eps  = (xin - xk) * invwk;
            const float et   = eps * (1.0f - eps);
            const float e2   = eps * eps;
            const float beta = sk + (dk1 + dk - 2.0f * sk) * et;
            const float alp  = hk * (sk * e2 + dk * et);
            yv[tt] = mask ? xv : (yk + __fdividef(alp, beta));
            const float ome = 1.0f - eps;
            float ld = 2.0f * __logf(sk)
                     + __logf(dk1 * e2 + 2.0f * sk * et + dk * ome * ome)
                     - 2.0f * __logf(beta);
            ldsum += mask ? 0.0f : ld;
        }

        // outputs
        *(float2*)(out + grow + ts) = make_float2(yv[0], yv[1]);
        if (q < 2)
            *(float4*)(out + grow + 8 + q * 4) = ((const float4*)x2s)[r * 2 + q];

        ldsum += __shfl_xor_sync(0xffffffffu, ldsum, 1);
        ldsum += __shfl_xor_sync(0xffffffffu, ldsum, 2);
        if (q == 0)
            out[(size_t)B * 16 + row0 + r] = ldsum;
    }
}

extern "C" void kernel_launch(void* const* d_in, const int* in_sizes, int n_in,
                              void* d_out, int out_size) {
    const float* x    = (const float*)d_in[0];
    const float* W0   = (const float*)d_in[1];
    const float* b0   = (const float*)d_in[2];
    const float* W1   = (const float*)d_in[3];
    const float* b1   = (const float*)d_in[4];
    const float* Wout = (const float*)d_in[5];
    const float* bout = (const float*)d_in[6];
    float* out = (float*)d_out;

    const int B = in_sizes[0] / 16;

    prep_w1<<<320, 256>>>(W1);
    prep_wo<<<240, 256>>>(Wout);
    prep_w0<<<40, 256>>>(W0);

    cudaFuncSetAttribute(coupling_hmma_kernel,
                         cudaFuncAttributeMaxDynamicSharedMemorySize, SMEM_BYTES);
    coupling_hmma_kernel<<<B / RB, NT, SMEM_BYTES>>>(x, b0, b1, bout, out, B);
}

// round 14
// speedup vs baseline: 1.4400x; 1.0460x over previous
#include <cuda_runtime.h>
#include <cuda_fp16.h>
#include <math.h>
#include <stdint.h>

#define NT    512
#define RB    128
#define AST   264            // A tile k-stride (fp16): 256 + 8 pad
#define WST   40             // W panel k-stride (fp16): 32 + 8 pad
#define RSTR  193
#define GRID  152            // persistent: one CTA per SM

// ---- smem layout (bytes) ----
#define OFF_A       0                   // 128*264*2 = 67584 fp16
#define OFF_WP      67584               // 3 stage slots * 40960
#define SLOT_B      40960
#define OFF_A0      190464              // dedicated: 128*40*2 = 10240
#define OFF_W0P     200704              // dedicated: 256*40*2 = 20480 (resident all tiles)
#define OFF_B0S     221184              // 256 f32
#define OFF_B1S     222208              // 256 f32
#define OFF_BOS     223232              // 192 f32
#define SMEM_BYTES  224000
// raw buffer (epilogue2): 128*193*4 = 98816 at sm[0], overlaps A+slot0 (dead then)

#define PAN1_B 20480                    // one K=32 GEMM1 panel
#define PAN2_B 15360
#define STG1_B 40960                    // GEMM1 stage (2 panels)
#define STG2_B 30720

// ---- prebuilt fp16 weight panels ----
__device__ __align__(16) __half g_w1[8 * 256 * 40];
__device__ __align__(16) __half g_wo[8 * 192 * 40];
__device__ __align__(16) __half g_w0[256 * 40];     // [W0hi | W0hi | W0lo | 0] k-layout

// ---- helpers ----
__device__ __forceinline__ uint32_t smem_u32(const void* p) {
    uint32_t a;
    asm("{ .reg .u64 t; cvta.to.shared.u64 t, %1; cvt.u32.u64 %0, t; }" : "=r"(a) : "l"(p));
    return a;
}
__device__ __forceinline__ void cp16(uint32_t dst, const void* src) {
    asm volatile("cp.async.cg.shared.global [%0], [%1], 16;" :: "r"(dst), "l"(src));
}
#define CP_COMMIT() asm volatile("cp.async.commit_group;")
#define CP_WAIT0()  asm volatile("cp.async.wait_group 0;")
#define CP_WAIT1()  asm volatile("cp.async.wait_group 1;")

__device__ __forceinline__ void mma16(float* d, uint32_t a0, uint32_t a1, uint32_t a2, uint32_t a3,
                                      uint32_t b0, uint32_t b1) {
    asm volatile("mma.sync.aligned.m16n8k16.row.col.f32.f16.f16.f32 "
                 "{%0,%1,%2,%3}, {%4,%5,%6,%7}, {%8,%9}, {%0,%1,%2,%3};"
                 : "+f"(d[0]), "+f"(d[1]), "+f"(d[2]), "+f"(d[3])
                 : "r"(a0), "r"(a1), "r"(a2), "r"(a3), "r"(b0), "r"(b1));
}
__device__ __forceinline__ void ldsm4(uint32_t& r0, uint32_t& r1, uint32_t& r2, uint32_t& r3,
                                      uint32_t addr) {
    asm volatile("ldmatrix.sync.aligned.m8n8.x4.shared.b16 {%0,%1,%2,%3}, [%4];"
                 : "=r"(r0), "=r"(r1), "=r"(r2), "=r"(r3) : "r"(addr));
}

// ---- fast transcendentals ----
__device__ __forceinline__ float flog1p(float x) {       // x >= 0
    return (x < 1e-2f) ? x * (1.0f - 0.5f * x) : __logf(1.0f + x);
}
__device__ __forceinline__ float softplusf(float v) {
    return fmaxf(v, 0.0f) + flog1p(__expf(-fabsf(v)));
}

// k-panel compute (K=32) via ldmatrix; 2 m-tiles (32-row warp tile)
template<int NTILES, int ASTRIDE>
__device__ __forceinline__ void panel_compute(uint32_t aLane, uint32_t wLane, float d[2][8][4])
{
    #pragma unroll
    for (int ks = 0; ks < 2; ks++) {
        const uint32_t aK = aLane + ks * 32;
        const uint32_t wK = wLane + ks * 32;
        uint32_t a[2][4];
        #pragma unroll
        for (int mt = 0; mt < 2; mt++)
            ldsm4(a[mt][0], a[mt][1], a[mt][2], a[mt][3], aK + mt * (16 * ASTRIDE * 2));
        #pragma unroll
        for (int ntp = 0; ntp < NTILES / 2; ntp++) {
            uint32_t b0, b1, b2, b3;
            ldsm4(b0, b1, b2, b3, wK + ntp * (16 * WST * 2));
            #pragma unroll
            for (int mt = 0; mt < 2; mt++) {
                mma16(d[mt][2 * ntp],     a[mt][0], a[mt][1], a[mt][2], a[mt][3], b0, b1);
                mma16(d[mt][2 * ntp + 1], a[mt][0], a[mt][1], a[mt][2], a[mt][3], b2, b3);
            }
        }
    }
}

// ---- prep kernels ----
__global__ void prep_w1(const float* __restrict__ W1) {
    int idx = blockIdx.x * blockDim.x + threadIdx.x;      // 81920
    int p = idx / 10240, rem = idx % 10240;
    int n = rem / 40, kk = rem % 40;
    float w = (kk < 32) ? W1[(p * 32 + kk) * 256 + n] : 0.0f;
    g_w1[idx] = __float2half_rn(w);
}
__global__ void prep_wo(const float* __restrict__ Wout) {
    int idx = blockIdx.x * blockDim.x + threadIdx.x;      // 61440
    int p = idx / 7680, rem = idx % 7680;
    int n = rem / 40, kk = rem % 40;
    float w = (kk < 32 && n < 184) ? Wout[(p * 32 + kk) * 184 + n] : 0.0f;
    g_wo[idx] = __float2half_rn(w);
}
__global__ void prep_w0(const float* __restrict__ W0) {
    int idx = blockIdx.x * blockDim.x + threadIdx.x;      // 10240
    int n = idx / 40, kk = idx % 40;
    __half v = __float2half_rn(0.0f);
    if (kk < 16) {
        float w = W0[(kk & 7) * 256 + n];
        v = __float2half_rn(w);
    } else if (kk < 24) {
        float w = W0[(kk - 16) * 256 + n];
        __half h = __float2half_rn(w);
        v = __float2half_rn(w - __half2float(h));
    }
    g_w0[idx] = v;
}

// ---- A0 staging: exact hi/lo split of x2 rows of tile t (tid<128 only) ----
__device__ __forceinline__ void stage_a0(char* sm, const float* __restrict__ x,
                                         int row0, int tid) {
    if (tid < RB) {
        const float4* xp = (const float4*)(x + (size_t)(row0 + tid) * 16);
        float4 xc = xp[2], xd = xp[3];
        float xv[8] = {xc.x, xc.y, xc.z, xc.w, xd.x, xd.y, xd.z, xd.w};
        __half2* a0 = (__half2*)(sm + OFF_A0 + tid * 40 * 2);
        #pragma unroll
        for (int j = 0; j < 8; j += 2) {
            __half h0 = __float2half_rn(xv[j]);
            __half h1 = __float2half_rn(xv[j + 1]);
            __half l0 = __float2half_rn(xv[j] - __half2float(h0));
            __half l1 = __float2half_rn(xv[j + 1] - __half2float(h1));
            a0[j / 2]      = __half2(h0, h1);   // k 0..7  : x2hi
            a0[4 + j / 2]  = __half2(l0, l1);   // k 8..15 : x2lo
            a0[8 + j / 2]  = __half2(h0, h1);   // k 16..23: x2hi (vs W0lo)
            a0[12 + j / 2] = __half2(__float2half_rn(0.f), __float2half_rn(0.f));
            a0[16 + j / 2] = __half2(__float2half_rn(0.f), __float2half_rn(0.f));
        }
    }
}

// ---- main persistent kernel ----
__global__ void __launch_bounds__(NT, 1)
coupling_hmma_kernel(const float* __restrict__ x,
                     const float* __restrict__ b0,
                     const float* __restrict__ b1,
                     const float* __restrict__ bout,
                     float* __restrict__ out,
                     int B, int nTiles)
{
    extern __shared__ char sm[];
    const int tid = threadIdx.x;
    const int lane = tid & 31;
    const int wid = tid >> 5;
    const int mw = wid & 3, nw = wid >> 2;
    const int qr = lane >> 2, qc = (lane & 3) * 2;
    const uint32_t sm_u32 = smem_u32(sm);
    const uint32_t wp_u32 = sm_u32 + OFF_WP;

    float* b0s = (float*)(sm + OFF_B0S);
    float* b1s = (float*)(sm + OFF_B1S);
    float* bos = (float*)(sm + OFF_BOS);

    const int aRow = (lane & 15);
    const int aKof = (lane >> 4) * 8;
    const int wRow = (lane & 7) + ((lane >> 4) * 8);
    const int wKof = ((lane >> 3) & 1) * 8;
    const uint32_t aLaneA = sm_u32 + OFF_A + (((mw * 32 + aRow) * AST) + aKof) * 2;
    const uint32_t aLane0 = sm_u32 + OFF_A0 + (((mw * 32 + aRow) * 40) + aKof) * 2;
    const uint32_t wRel1 = (((nw * 64 + wRow) * WST) + wKof) * 2;
    const uint32_t wRel2 = (((nw * 48 + wRow) * WST) + wKof) * 2;
    const uint32_t wLane0 = sm_u32 + OFF_W0P + wRel1;

    // ---- one-time prologue ----
    for (int i = tid; i < STG1_B / 16; i += NT)
        cp16(wp_u32 + i * 16, (const char*)g_w1 + i * 16);
    CP_COMMIT();
    for (int i = tid; i < STG1_B / 16; i += NT)
        cp16(wp_u32 + SLOT_B + i * 16, (const char*)g_w1 + STG1_B + i * 16);
    CP_COMMIT();
    for (int i = tid; i < 1280; i += NT)
        cp16(sm_u32 + OFF_W0P + i * 16, (const char*)g_w0 + i * 16);
    CP_COMMIT();

    for (int i = tid; i < 256; i += NT) { b0s[i] = b0[i]; b1s[i] = b1[i]; }
    for (int i = tid; i < 192; i += NT) bos[i] = (i < 184) ? bout[i] : 0.0f;
    stage_a0(sm, x, blockIdx.x * RB, tid);
    CP_WAIT0();
    __syncthreads();      // W0P/A0/stages 0,1/consts all ready

    // ---- persistent tile loop ----
    for (int t = blockIdx.x; t < nTiles; t += GRID) {
        const int row0 = t * RB;
        const bool more = (t + GRID < nTiles);

        float d[2][8][4];
        #pragma unroll
        for (int mt = 0; mt < 2; mt++)
            #pragma unroll
            for (int nt = 0; nt < 8; nt++)
                #pragma unroll
                for (int i = 0; i < 4; i++) d[mt][nt][i] = 0.0f;

        // ---- GEMM0 (A0 + resident W0P); covers in-flight stage-0 load ----
        panel_compute<8, 40>(aLane0, wLane0, d);

        // ---- epilogue0: h0 = relu(d + b0) -> fp16 A tile ----
        // (A region overlapped prev tile's rawS — ordered by the spline-end sync)
        #pragma unroll
        for (int mt = 0; mt < 2; mt++) {
            const int r0 = mw * 32 + mt * 16 + qr;
            #pragma unroll
            for (int nt = 0; nt < 8; nt++) {
                const int c = nw * 64 + nt * 8 + qc;
                const float g0 = b0s[c], g1 = b0s[c + 1];
                float v00 = fmaxf(d[mt][nt][0] + g0, 0.f);
                float v01 = fmaxf(d[mt][nt][1] + g1, 0.f);
                float v10 = fmaxf(d[mt][nt][2] + g0, 0.f);
                float v11 = fmaxf(d[mt][nt][3] + g1, 0.f);
                *(__half2*)(sm + OFF_A + ((size_t)r0 * AST + c) * 2) = __floats2half2_rn(v00, v01);
                *(__half2*)(sm + OFF_A + ((size_t)(r0 + 8) * AST + c) * 2) = __floats2half2_rn(v10, v11);
                #pragma unroll
                for (int i = 0; i < 4; i++) d[mt][nt][i] = 0.0f;
            }
        }

        // ---- stage pipeline: s 0..3 = GEMM1, s 4..7 = GEMM2 ----
        for (int s = 0; s < 8; s++) {
            if (s == 0) { CP_WAIT0(); } else { CP_WAIT1(); }
            __syncthreads();

            if (s == 4) {
                // epilogue1: h1 = relu(d + b1) -> fp16 A tile
                #pragma unroll
                for (int mt = 0; mt < 2; mt++) {
                    const int r0 = mw * 32 + mt * 16 + qr;
                    #pragma unroll
                    for (int nt = 0; nt < 8; nt++) {
                        const int c = nw * 64 + nt * 8 + qc;
                        const float g0 = b1s[c], g1 = b1s[c + 1];
                        float v00 = fmaxf(d[mt][nt][0] + g0, 0.f);
                        float v01 = fmaxf(d[mt][nt][1] + g1, 0.f);
                        float v10 = fmaxf(d[mt][nt][2] + g0, 0.f);
                        float v11 = fmaxf(d[mt][nt][3] + g1, 0.f);
                        *(__half2*)(sm + OFF_A + ((size_t)r0 * AST + c) * 2) = __floats2half2_rn(v00, v01);
                        *(__half2*)(sm + OFF_A + ((size_t)(r0 + 8) * AST + c) * 2) = __floats2half2_rn(v10, v11);
                        #pragma unroll
                        for (int i = 0; i < 4; i++) d[mt][nt][i] = 0.0f;
                    }
                }
                __syncthreads();
            }

            if (s + 2 < 8) {
                const int ns = s + 2;
                uint32_t dst = wp_u32 + (ns % 3) * SLOT_B;
                if (ns < 4) {
                    const char* src = (const char*)g_w1 + (size_t)ns * STG1_B;
                    for (int i = tid; i < STG1_B / 16; i += NT) cp16(dst + i * 16, src + i * 16);
                } else {
                    const char* src = (const char*)g_wo + (size_t)(ns - 4) * STG2_B;
                    for (int i = tid; i < STG2_B / 16; i += NT) cp16(dst + i * 16, src + i * 16);
                }
            }
            CP_COMMIT();

            const uint32_t slot = wp_u32 + (s % 3) * SLOT_B;
            if (s < 4) {
                panel_compute<8, AST>(aLaneA + (2 * s) * 64,     slot + wRel1, d);
                panel_compute<8, AST>(aLaneA + (2 * s + 1) * 64, slot + PAN1_B + wRel1, d);
            } else {
                panel_compute<6, AST>(aLaneA + (2 * s - 8) * 64, slot + wRel2, d);
                panel_compute<6, AST>(aLaneA + (2 * s - 7) * 64, slot + PAN2_B + wRel2, d);
            }
        }
        __syncthreads();   // all GEMM2 A/W reads done (slot0 read @s=6, slot1 @s=7, A @s=7)

        // ---- epilogue2: raw = d + bout -> smem f32 [128][193] (overlaps A+slot0) ----
        float* rawS = (float*)sm;
        #pragma unroll
        for (int mt = 0; mt < 2; mt++) {
            const int r0 = mw * 32 + mt * 16 + qr;
            #pragma unroll
            for (int nt = 0; nt < 6; nt++) {
                const int c = nw * 48 + nt * 8 + qc;
                rawS[r0 * RSTR + c]           = d[mt][nt][0] + bos[c];
                rawS[r0 * RSTR + c + 1]       = d[mt][nt][1] + bos[c + 1];
                rawS[(r0 + 8) * RSTR + c]     = d[mt][nt][2] + bos[c];
                rawS[(r0 + 8) * RSTR + c + 1] = d[mt][nt][3] + bos[c + 1];
            }
        }

        // cross-tile prefetch (slot1 free, A0 region free): next stage1 + next A0
        if (more) {
            const char* src = (const char*)g_w1 + STG1_B;
            for (int i = tid; i < STG1_B / 16; i += NT)
                cp16(wp_u32 + SLOT_B + i * 16, src + i * 16);
            stage_a0(sm, x, (t + GRID) * RB, tid);
        }
        CP_COMMIT();
        __syncthreads();   // rawS + next-A0 visible

        // ---- spline: 4 threads/row, 2 transforms each ----
        {
            const int r = tid >> 2;
            const int q = tid & 3;
            const int ts = q * 2;
            const size_t grow = (size_t)(row0 + r) * 16;
            const float2 x1p = *(const float2*)(x + grow + ts);
            const float x1v[2] = {x1p.x, x1p.y};
            const float CNST = logf(expf(1.0f - 1e-4f) - 1.0f);
            float yv[2];
            float ldsum = 0.0f;

            #pragma unroll
            for (int tt = 0; tt < 2; tt++) {
                const float* raw = rawS + r * RSTR + (ts + tt) * 23;
                const float xv = x1v[tt];

                float rw[8], rh[8];
                #pragma unroll
                for (int c = 0; c < 8; c++) { rw[c] = raw[c]; rh[c] = raw[8 + c]; }

                float m = rw[0];
                #pragma unroll
                for (int c = 1; c < 8; c++) m = fmaxf(m, rw[c]);
                float sum = 0.0f, ew[8];
                #pragma unroll
                for (int c = 0; c < 8; c++) { ew[c] = __expf(rw[c] - m); sum += ew[c]; }
                float inv = __fdividef(1.0f, sum);
                float wdt[8];
                #pragma unroll
                for (int c = 0; c < 8; c++) wdt[c] = 2.0f * (1e-4f + (1.0f - 8e-4f) * ew[c] * inv);

                m = rh[0];
                #pragma unroll
                for (int c = 1; c < 8; c++) m = fmaxf(m, rh[c]);
                sum = 0.0f;
                #pragma unroll
                for (int c = 0; c < 8; c++) { ew[c] = __expf(rh[c] - m); sum += ew[c]; }
                inv = __fdividef(1.0f, sum);
                float hgt[8];
                #pragma unroll
                for (int c = 0; c < 8; c++) hgt[c] = 2.0f * (1e-4f + (1.0f - 8e-4f) * ew[c] * inv);

                float dv[9];
                dv[0] = 1.0f; dv[8] = 1.0f;
                #pragma unroll
                for (int c = 0; c < 7; c++) dv[c + 1] = softplusf(raw[16 + c] + CNST) + 1e-4f;

                const bool mask = (xv <= -0.999f) || (xv >= 0.999f);
                const float xin = mask ? 0.0f : xv;

                float cx = -1.0f, cy = -1.0f;
                float xk = -1.0f, yk = -1.0f, wk = wdt[0], hk = hgt[0], dk = dv[0], dk1 = dv[1];
                #pragma unroll
                for (int i = 0; i < 8; i++) {
                    if (cx <= xin) { xk = cx; yk = cy; wk = wdt[i]; hk = hgt[i]; dk = dv[i]; dk1 = dv[i + 1]; }
                    cx += wdt[i]; cy += hgt[i];
                }

                const float invwk = __fdividef(1.0f, wk);
                const float sk   = hk * invwk;
                const float eps  = (xin - xk) * invwk;
                const float et   = eps * (1.0f - eps);
                const float e2   = eps * eps;
                const float beta = sk + (dk1 + dk - 2.0f * sk) * et;
                const float alp  = hk * (sk * e2 + dk * et);
                yv[tt] = mask ? xv : (yk + __fdividef(alp, beta));
                const float ome = 1.0f - eps;
                float ld = 2.0f * __logf(sk)
                         + __logf(dk1 * e2 + 2.0f * sk * et + dk * ome * ome)
                         - 2.0f * __logf(beta);
                ldsum += mask ? 0.0f : ld;
            }

            *(float2*)(out + grow + ts) = make_float2(yv[0], yv[1]);
            if (q < 2)
                *(float4*)(out + grow + 8 + q * 4) = *(const float4*)(x + grow + 8 + q * 4);

            ldsum += __shfl_xor_sync(0xffffffffu, ldsum, 1);
            ldsum += __shfl_xor_sync(0xffffffffu, ldsum, 2);
            if (q == 0)
                out[(size_t)B * 16 + row0 + r] = ldsum;
        }
        __syncthreads();   // spline rawS reads done -> A + slot0 free

        // issue next tile's stage0 into slot0 (latency covered by next GEMM0+epi0)
        if (more) {
            for (int i = tid; i < STG1_B / 16; i += NT)
                cp16(wp_u32 + i * 16, (const char*)g_w1 + i * 16);
        }
        CP_COMMIT();
    }
}

extern "C" void kernel_launch(void* const* d_in, const int* in_sizes, int n_in,
                              void* d_out, int out_size) {
    const float* x    = (const float*)d_in[0];
    const float* W0   = (const float*)d_in[1];
    const float* b0   = (const float*)d_in[2];
    const float* W1   = (const float*)d_in[3];
    const float* b1   = (const float*)d_in[4];
    const float* Wout = (const float*)d_in[5];
    const float* bout = (const float*)d_in[6];
    float* out = (float*)d_out;

    const int B = in_sizes[0] / 16;
    const int nTiles = B / RB;

    prep_w1<<<320, 256>>>(W1);
    prep_wo<<<240, 256>>>(Wout);
    prep_w0<<<40, 256>>>(W0);

    cudaFuncSetAttribute(coupling_hmma_kernel,
                         cudaFuncAttributeMaxDynamicSharedMemorySize, SMEM_BYTES);
    coupling_hmma_kernel<<<GRID, NT, SMEM_BYTES>>>(x, b0, b1, bout, out, B, nTiles);
}

// round 15
// speedup vs baseline: 1.5279x; 1.0611x over previous
#include <cuda_runtime.h>
#include <cuda_fp16.h>
#include <math.h>
#include <stdint.h>

#define NT    512
#define RB    192
#define AST   264            // A tile k-stride (fp16): 256 + 8 pad
#define WST   40             // W panel k-stride: 32 + 8 pad
#define RSTR  193
#define GRID  152            // persistent: one CTA per SM

// ---- smem layout (bytes) ----
#define OFF_A       0                   // 192*264*2 = 101376 fp16
#define OFF_WP      101376              // 2 stage slots * 40960
#define SLOT_B      40960
#define OFF_W0P     183296              // 256*40*2 = 20480 (resident)
#define OFF_A0      203776              // 192*40*2 = 15360
#define OFF_B0S     219136              // 256 f32
#define OFF_B1S     220160              // 256 f32
#define OFF_BOS     221184              // 192 f32
#define SMEM_BYTES  221952
// rawS (epilogue2): 192*193*4 = 148224 at sm[0], overlaps A+both slots (dead then)

#define PAN1_B 20480
#define PAN2_B 15360
#define STG1_B 40960                    // GEMM1 stage (2 panels)
#define STG2_B 30720                    // GEMM2 stage (2 panels)

// ---- prebuilt fp16 weight panels ----
__device__ __align__(16) __half g_w1[8 * 256 * 40];
__device__ __align__(16) __half g_wo[8 * 192 * 40];
__device__ __align__(16) __half g_w0[256 * 40];     // [W0hi | W0hi | W0lo | 0]

// ---- helpers ----
__device__ __forceinline__ uint32_t smem_u32(const void* p) {
    uint32_t a;
    asm("{ .reg .u64 t; cvta.to.shared.u64 t, %1; cvt.u32.u64 %0, t; }" : "=r"(a) : "l"(p));
    return a;
}
__device__ __forceinline__ void cp16(uint32_t dst, const void* src) {
    asm volatile("cp.async.cg.shared.global [%0], [%1], 16;" :: "r"(dst), "l"(src));
}
#define CP_COMMIT() asm volatile("cp.async.commit_group;")
#define CP_WAIT0()  asm volatile("cp.async.wait_group 0;")

__device__ __forceinline__ void mma16(float* d, uint32_t a0, uint32_t a1, uint32_t a2, uint32_t a3,
                                      uint32_t b0, uint32_t b1) {
    asm volatile("mma.sync.aligned.m16n8k16.row.col.f32.f16.f16.f32 "
                 "{%0,%1,%2,%3}, {%4,%5,%6,%7}, {%8,%9}, {%0,%1,%2,%3};"
                 : "+f"(d[0]), "+f"(d[1]), "+f"(d[2]), "+f"(d[3])
                 : "r"(a0), "r"(a1), "r"(a2), "r"(a3), "r"(b0), "r"(b1));
}
__device__ __forceinline__ void ldsm4(uint32_t& r0, uint32_t& r1, uint32_t& r2, uint32_t& r3,
                                      uint32_t addr) {
    asm volatile("ldmatrix.sync.aligned.m8n8.x4.shared.b16 {%0,%1,%2,%3}, [%4];"
                 : "=r"(r0), "=r"(r1), "=r"(r2), "=r"(r3) : "r"(addr));
}

// ---- fast transcendentals ----
__device__ __forceinline__ float flog1p(float x) {       // x >= 0
    return (x < 1e-2f) ? x * (1.0f - 0.5f * x) : __logf(1.0f + x);
}
__device__ __forceinline__ float softplusf(float v) {
    return fmaxf(v, 0.0f) + flog1p(__expf(-fabsf(v)));
}

// K=32 panel via ldmatrix; 3 m-tiles (48-row warp tile)
template<int NTILES, int ASTRIDE>
__device__ __forceinline__ void panel_compute(uint32_t aLane, uint32_t wLane, float d[3][8][4])
{
    #pragma unroll
    for (int ks = 0; ks < 2; ks++) {
        const uint32_t aK = aLane + ks * 32;
        const uint32_t wK = wLane + ks * 32;
        uint32_t a[3][4];
        #pragma unroll
        for (int mt = 0; mt < 3; mt++)
            ldsm4(a[mt][0], a[mt][1], a[mt][2], a[mt][3], aK + mt * (16 * ASTRIDE * 2));
        #pragma unroll
        for (int ntp = 0; ntp < NTILES / 2; ntp++) {
            uint32_t b0, b1, b2, b3;
            ldsm4(b0, b1, b2, b3, wK + ntp * (16 * WST * 2));
            #pragma unroll
            for (int mt = 0; mt < 3; mt++) {
                mma16(d[mt][2 * ntp],     a[mt][0], a[mt][1], a[mt][2], a[mt][3], b0, b1);
                mma16(d[mt][2 * ntp + 1], a[mt][0], a[mt][1], a[mt][2], a[mt][3], b2, b3);
            }
        }
    }
}

// ---- prep kernels ----
__global__ void prep_w1(const float* __restrict__ W1) {
    int idx = blockIdx.x * blockDim.x + threadIdx.x;      // 81920
    int p = idx / 10240, rem = idx % 10240;
    int n = rem / 40, kk = rem % 40;
    float w = (kk < 32) ? W1[(p * 32 + kk) * 256 + n] : 0.0f;
    g_w1[idx] = __float2half_rn(w);
}
__global__ void prep_wo(const float* __restrict__ Wout) {
    int idx = blockIdx.x * blockDim.x + threadIdx.x;      // 61440
    int p = idx / 7680, rem = idx % 7680;
    int n = rem / 40, kk = rem % 40;
    float w = (kk < 32 && n < 184) ? Wout[(p * 32 + kk) * 184 + n] : 0.0f;
    g_wo[idx] = __float2half_rn(w);
}
__global__ void prep_w0(const float* __restrict__ W0) {
    int idx = blockIdx.x * blockDim.x + threadIdx.x;      // 10240
    int n = idx / 40, kk = idx % 40;
    __half v = __float2half_rn(0.0f);
    if (kk < 16) {
        float w = W0[(kk & 7) * 256 + n];
        v = __float2half_rn(w);
    } else if (kk < 24) {
        float w = W0[(kk - 16) * 256 + n];
        __half h = __float2half_rn(w);
        v = __float2half_rn(w - __half2float(h));
    }
    g_w0[idx] = v;
}

// ---- A0 staging: exact hi/lo split of x2 rows (tid<192, row clamped to B-1) ----
__device__ __forceinline__ void stage_a0(char* sm, const float* __restrict__ x,
                                         int row0, int tid, int B) {
    if (tid < RB) {
        const int rr = min(row0 + tid, B - 1);
        const float4* xp = (const float4*)(x + (size_t)rr * 16);
        float4 xc = xp[2], xd = xp[3];
        float xv[8] = {xc.x, xc.y, xc.z, xc.w, xd.x, xd.y, xd.z, xd.w};
        __half2* a0 = (__half2*)(sm + OFF_A0 + tid * 40 * 2);
        #pragma unroll
        for (int j = 0; j < 8; j += 2) {
            __half h0 = __float2half_rn(xv[j]);
            __half h1 = __float2half_rn(xv[j + 1]);
            __half l0 = __float2half_rn(xv[j] - __half2float(h0));
            __half l1 = __float2half_rn(xv[j + 1] - __half2float(h1));
            a0[j / 2]      = __half2(h0, h1);
            a0[4 + j / 2]  = __half2(l0, l1);
            a0[8 + j / 2]  = __half2(h0, h1);
            a0[12 + j / 2] = __half2(__float2half_rn(0.f), __float2half_rn(0.f));
            a0[16 + j / 2] = __half2(__float2half_rn(0.f), __float2half_rn(0.f));
        }
    }
}

// ---- main persistent kernel ----
__global__ void __launch_bounds__(NT, 1)
coupling_hmma_kernel(const float* __restrict__ x,
                     const float* __restrict__ b0,
                     const float* __restrict__ b1,
                     const float* __restrict__ bout,
                     float* __restrict__ out,
                     int B, int nTiles)
{
    extern __shared__ char sm[];
    const int tid = threadIdx.x;
    const int lane = tid & 31;
    const int wid = tid >> 5;
    const int mw = wid & 3, nw = wid >> 2;
    const int qr = lane >> 2, qc = (lane & 3) * 2;
    const uint32_t sm_u32 = smem_u32(sm);
    const uint32_t wp_u32 = sm_u32 + OFF_WP;

    float* b0s = (float*)(sm + OFF_B0S);
    float* b1s = (float*)(sm + OFF_B1S);
    float* bos = (float*)(sm + OFF_BOS);

    const int aRow = (lane & 15);
    const int aKof = (lane >> 4) * 8;
    const int wRow = (lane & 7) + ((lane >> 4) * 8);
    const int wKof = ((lane >> 3) & 1) * 8;
    const uint32_t aLaneA = sm_u32 + OFF_A + (((mw * 48 + aRow) * AST) + aKof) * 2;
    const uint32_t aLane0 = sm_u32 + OFF_A0 + (((mw * 48 + aRow) * 40) + aKof) * 2;
    const uint32_t wRel1 = (((nw * 64 + wRow) * WST) + wKof) * 2;
    const uint32_t wRel2 = (((nw * 48 + wRow) * WST) + wKof) * 2;
    const uint32_t wLane0 = sm_u32 + OFF_W0P + wRel1;

    // ---- one-time prologue: stage0 (slot0), W0P; consts; first A0 ----
    for (int i = tid; i < STG1_B / 16; i += NT)
        cp16(wp_u32 + i * 16, (const char*)g_w1 + i * 16);
    for (int i = tid; i < 1280; i += NT)
        cp16(sm_u32 + OFF_W0P + i * 16, (const char*)g_w0 + i * 16);
    CP_COMMIT();

    for (int i = tid; i < 256; i += NT) { b0s[i] = b0[i]; b1s[i] = b1[i]; }
    for (int i = tid; i < 192; i += NT) bos[i] = (i < 184) ? bout[i] : 0.0f;
    stage_a0(sm, x, blockIdx.x * RB, tid, B);
    __syncthreads();

    // ---- persistent tile loop ----
    for (int t = blockIdx.x; t < nTiles; t += GRID) {
        const int row0 = t * RB;
        const int rowsLeft = min(RB, B - row0);
        const bool more = (t + GRID < nTiles);

        float d[3][8][4];
        #pragma unroll
        for (int mt = 0; mt < 3; mt++)
            #pragma unroll
            for (int nt = 0; nt < 8; nt++)
                #pragma unroll
                for (int i = 0; i < 4; i++) d[mt][nt][i] = 0.0f;

        // ---- GEMM0 (A0 x resident W0P); covers in-flight stage0 load ----
        panel_compute<8, 40>(aLane0, wLane0, d);

        // ---- epilogue0: h0 = relu(d + b0) -> fp16 A tile ----
        #pragma unroll
        for (int mt = 0; mt < 3; mt++) {
            const int r0 = mw * 48 + mt * 16 + qr;
            #pragma unroll
            for (int nt = 0; nt < 8; nt++) {
                const int c = nw * 64 + nt * 8 + qc;
                const float g0 = b0s[c], g1 = b0s[c + 1];
                float v00 = fmaxf(d[mt][nt][0] + g0, 0.f);
                float v01 = fmaxf(d[mt][nt][1] + g1, 0.f);
                float v10 = fmaxf(d[mt][nt][2] + g0, 0.f);
                float v11 = fmaxf(d[mt][nt][3] + g1, 0.f);
                *(__half2*)(sm + OFF_A + ((size_t)r0 * AST + c) * 2) = __floats2half2_rn(v00, v01);
                *(__half2*)(sm + OFF_A + ((size_t)(r0 + 8) * AST + c) * 2) = __floats2half2_rn(v10, v11);
                #pragma unroll
                for (int i = 0; i < 4; i++) d[mt][nt][i] = 0.0f;
            }
        }

        // ---- stage pipeline: s 0..3 = GEMM1, s 4..7 = GEMM2 (2 slots, wait-all) ----
        for (int s = 0; s < 8; s++) {
            CP_WAIT0();
            __syncthreads();

            if (s == 4) {
                // epilogue1: h1 = relu(d + b1) -> fp16 A tile
                #pragma unroll
                for (int mt = 0; mt < 3; mt++) {
                    const int r0 = mw * 48 + mt * 16 + qr;
                    #pragma unroll
                    for (int nt = 0; nt < 8; nt++) {
                        const int c = nw * 64 + nt * 8 + qc;
                        const float g0 = b1s[c], g1 = b1s[c + 1];
                        float v00 = fmaxf(d[mt][nt][0] + g0, 0.f);
                        float v01 = fmaxf(d[mt][nt][1] + g1, 0.f);
                        float v10 = fmaxf(d[mt][nt][2] + g0, 0.f);
                        float v11 = fmaxf(d[mt][nt][3] + g1, 0.f);
                        *(__half2*)(sm + OFF_A + ((size_t)r0 * AST + c) * 2) = __floats2half2_rn(v00, v01);
                        *(__half2*)(sm + OFF_A + ((size_t)(r0 + 8) * AST + c) * 2) = __floats2half2_rn(v10, v11);
                        #pragma unroll
                        for (int i = 0; i < 4; i++) d[mt][nt][i] = 0.0f;
                    }
                }
                __syncthreads();
            }

            // issue stage s+1 into slot (s+1)&1 (its occupant s-1 consumed by the wait+sync)
            if (s + 1 < 8) {
                const int ns = s + 1;
                uint32_t dst = wp_u32 + (ns & 1) * SLOT_B;
                if (ns < 4) {
                    const char* src = (const char*)g_w1 + (size_t)ns * STG1_B;
                    for (int i = tid; i < STG1_B / 16; i += NT) cp16(dst + i * 16, src + i * 16);
                } else {
                    const char* src = (const char*)g_wo + (size_t)(ns - 4) * STG2_B;
                    for (int i = tid; i < STG2_B / 16; i += NT) cp16(dst + i * 16, src + i * 16);
                }
            }
            CP_COMMIT();

            const uint32_t slot = wp_u32 + (s & 1) * SLOT_B;
            if (s < 4) {
                panel_compute<8, AST>(aLaneA + (2 * s) * 64,     slot + wRel1, d);
                panel_compute<8, AST>(aLaneA + (2 * s + 1) * 64, slot + PAN1_B + wRel1, d);
            } else {
                panel_compute<6, AST>(aLaneA + (2 * s - 8) * 64, slot + wRel2, d);
                panel_compute<6, AST>(aLaneA + (2 * s - 7) * 64, slot + PAN2_B + wRel2, d);
            }
        }
        __syncthreads();   // all GEMM2 A/W reads done

        // ---- epilogue2: raw = d + bout -> smem f32 [192][193] (overlaps A+slots) ----
        float* rawS = (float*)sm;
        #pragma unroll
        for (int mt = 0; mt < 3; mt++) {
            const int r0 = mw * 48 + mt * 16 + qr;
            #pragma unroll
            for (int nt = 0; nt < 6; nt++) {
                const int c = nw * 48 + nt * 8 + qc;
                rawS[r0 * RSTR + c]           = d[mt][nt][0] + bos[c];
                rawS[r0 * RSTR + c + 1]       = d[mt][nt][1] + bos[c + 1];
                rawS[(r0 + 8) * RSTR + c]     = d[mt][nt][2] + bos[c];
                rawS[(r0 + 8) * RSTR + c + 1] = d[mt][nt][3] + bos[c + 1];
            }
        }
        if (more) stage_a0(sm, x, (t + GRID) * RB, tid, B);   // A0 region free
        __syncthreads();   // rawS + next-A0 visible

        // ---- spline: tid<384 -> 2 threads/row x 4 transforms; tid>=384 -> x2 passthrough ----
        if (tid < 384) {
            const int r = tid >> 1;
            const int ts = (tid & 1) * 4;
            const int grow = row0 + r;
            const bool valid = (r < rowsLeft);
            const size_t gx = (size_t)min(grow, B - 1) * 16;
            const float4 x1q = *(const float4*)(x + gx + ts);
            const float x1v[4] = {x1q.x, x1q.y, x1q.z, x1q.w};
            const float CNST = logf(expf(1.0f - 1e-4f) - 1.0f);
            float yv[4];
            float ldsum = 0.0f;

            #pragma unroll
            for (int tt = 0; tt < 4; tt++) {
                const float* raw = rawS + r * RSTR + (ts + tt) * 23;
                const float xv = x1v[tt];

                float rw[8], rh[8];
                #pragma unroll
                for (int c = 0; c < 8; c++) { rw[c] = raw[c]; rh[c] = raw[8 + c]; }

                float m = rw[0];
                #pragma unroll
                for (int c = 1; c < 8; c++) m = fmaxf(m, rw[c]);
                float sum = 0.0f, ew[8];
                #pragma unroll
                for (int c = 0; c < 8; c++) { ew[c] = __expf(rw[c] - m); sum += ew[c]; }
                float inv = __fdividef(1.0f, sum);
                float wdt[8];
                #pragma unroll
                for (int c = 0; c < 8; c++) wdt[c] = 2.0f * (1e-4f + (1.0f - 8e-4f) * ew[c] * inv);

                m = rh[0];
                #pragma unroll
                for (int c = 1; c < 8; c++) m = fmaxf(m, rh[c]);
                sum = 0.0f;
                #pragma unroll
                for (int c = 0; c < 8; c++) { ew[c] = __expf(rh[c] - m); sum += ew[c]; }
                inv = __fdividef(1.0f, sum);
                float hgt[8];
                #pragma unroll
                for (int c = 0; c < 8; c++) hgt[c] = 2.0f * (1e-4f + (1.0f - 8e-4f) * ew[c] * inv);

                float dv[9];
                dv[0] = 1.0f; dv[8] = 1.0f;
                #pragma unroll
                for (int c = 0; c < 7; c++) dv[c + 1] = softplusf(raw[16 + c] + CNST) + 1e-4f;

                const bool mask = (xv <= -0.999f) || (xv >= 0.999f);
                const float xin = mask ? 0.0f : xv;

                float cx = -1.0f, cy = -1.0f;
                float xk = -1.0f, yk = -1.0f, wk = wdt[0], hk = hgt[0], dk = dv[0], dk1 = dv[1];
                #pragma unroll
                for (int i = 0; i < 8; i++) {
                    if (cx <= xin) { xk = cx; yk = cy; wk = wdt[i]; hk = hgt[i]; dk = dv[i]; dk1 = dv[i + 1]; }
                    cx += wdt[i]; cy += hgt[i];
                }

                const float invwk = __fdividef(1.0f, wk);
                const float sk   = hk * invwk;
                const float eps  = (xin - xk) * invwk;
                const float et   = eps * (1.0f - eps);
                const float e2   = eps * eps;
                const float beta = sk + (dk1 + dk - 2.0f * sk) * et;
                const float alp  = hk * (sk * e2 + dk * et);
                yv[tt] = mask ? xv : (yk + __fdividef(alp, beta));
                const float ome = 1.0f - eps;
                float ld = 2.0f * __logf(sk)
                         + __logf(dk1 * e2 + 2.0f * sk * et + dk * ome * ome)
                         - 2.0f * __logf(beta);
                ldsum += mask ? 0.0f : ld;
            }

            if (valid)
                *(float4*)(out + (size_t)grow * 16 + ts) = make_float4(yv[0], yv[1], yv[2], yv[3]);

            ldsum += __shfl_xor_sync(0xffffffffu, ldsum, 1);
            if ((tid & 1) == 0 && valid)
                out[(size_t)B * 16 + grow] = ldsum;
        } else {
            // x2 passthrough: 384 float4 tasks over 128 threads
            const int base = tid - 384;
            #pragma unroll
            for (int j = 0; j < 3; j++) {
                const int idx = base + j * 128;       // 0..383
                const int r = idx >> 1, q = idx & 1;
                const int grow = row0 + r;
                if (r < rowsLeft) {
                    const size_t gx = (size_t)grow * 16 + 8 + q * 4;
                    *(float4*)(out + gx) = *(const float4*)(x + gx);
                }
            }
        }
        __syncthreads();   // spline rawS reads done -> A + slots free

        // issue next tile's stage0 into slot0 (covered by next GEMM0+epi0)
        if (more) {
            for (int i = tid; i < STG1_B / 16; i += NT)
                cp16(wp_u32 + i * 16, (const char*)g_w1 + i * 16);
        }
        CP_COMMIT();
    }
}

extern "C" void kernel_launch(void* const* d_in, const int* in_sizes, int n_in,
                              void* d_out, int out_size) {
    const float* x    = (const float*)d_in[0];
    const float* W0   = (const float*)d_in[1];
    const float* b0   = (const float*)d_in[2];
    const float* W1   = (const float*)d_in[3];
    const float* b1   = (const float*)d_in[4];
    const float* Wout = (const float*)d_in[5];
    const float* bout = (const float*)d_in[6];
    float* out = (float*)d_out;

    const int B = in_sizes[0] / 16;
    const int nTiles = (B + RB - 1) / RB;

    prep_w1<<<320, 256>>>(W1);
    prep_wo<<<240, 256>>>(Wout);
    prep_w0<<<40, 256>>>(W0);

    cudaFuncSetAttribute(coupling_hmma_kernel,
                         cudaFuncAttributeMaxDynamicSharedMemorySize, SMEM_BYTES);
    coupling_hmma_kernel<<<GRID, NT, SMEM_BYTES>>>(x, b0, b1, bout, out, B, nTiles);
}

// round 16
// speedup vs baseline: 1.5615x; 1.0220x over previous
#include <cuda_runtime.h>
#include <cuda_fp16.h>
#include <math.h>
#include <stdint.h>

#define NT    512
#define RB    192
#define AST   264            // A tile k-stride (fp16): 256 + 8 pad
#define WST   40             // W panel k-stride: 32 + 8 pad
#define RSTR  193
#define GRID  152            // persistent: one CTA per SM

// ---- smem layout (bytes) ----
#define OFF_A       0                   // 192*264*2 = 101376 fp16
#define OFF_WP      101376              // 2 stage slots * 40960
#define SLOT_B      40960
#define OFF_W0P     183296              // 256*40*2 = 20480 (resident)
#define OFF_A0      203776              // 192*40*2 = 15360
#define OFF_B0S     219136              // 256 f32
#define OFF_B1S     220160              // 256 f32
#define OFF_BOS     221184              // 192 f32
#define SMEM_BYTES  221952
// rawS (epilogue2): 192*193*4 = 148224 at sm[0], overlaps A+both slots (dead then)

#define PAN1_B 20480
#define PAN2_B 15360
#define STG1_B 40960                    // GEMM1 stage (2 panels)
#define STG2_B 30720                    // GEMM2 stage (2 panels)

// ---- prebuilt fp16 weight panels ----
__device__ __align__(16) __half g_w1[8 * 256 * 40];
__device__ __align__(16) __half g_wo[8 * 192 * 40];
__device__ __align__(16) __half g_w0[256 * 40];     // [W0hi | W0hi | W0lo | 0]

// ---- helpers ----
__device__ __forceinline__ uint32_t smem_u32(const void* p) {
    uint32_t a;
    asm("{ .reg .u64 t; cvta.to.shared.u64 t, %1; cvt.u32.u64 %0, t; }" : "=r"(a) : "l"(p));
    return a;
}
__device__ __forceinline__ void cp16(uint32_t dst, const void* src) {
    asm volatile("cp.async.cg.shared.global [%0], [%1], 16;" :: "r"(dst), "l"(src));
}
#define CP_COMMIT() asm volatile("cp.async.commit_group;")
#define CP_WAIT0()  asm volatile("cp.async.wait_group 0;")

__device__ __forceinline__ void mma16(float* d, uint32_t a0, uint32_t a1, uint32_t a2, uint32_t a3,
                                      uint32_t b0, uint32_t b1) {
    asm volatile("mma.sync.aligned.m16n8k16.row.col.f32.f16.f16.f32 "
                 "{%0,%1,%2,%3}, {%4,%5,%6,%7}, {%8,%9}, {%0,%1,%2,%3};"
                 : "+f"(d[0]), "+f"(d[1]), "+f"(d[2]), "+f"(d[3])
                 : "r"(a0), "r"(a1), "r"(a2), "r"(a3), "r"(b0), "r"(b1));
}
__device__ __forceinline__ void ldsm4(uint32_t& r0, uint32_t& r1, uint32_t& r2, uint32_t& r3,
                                      uint32_t addr) {
    asm volatile("ldmatrix.sync.aligned.m8n8.x4.shared.b16 {%0,%1,%2,%3}, [%4];"
                 : "=r"(r0), "=r"(r1), "=r"(r2), "=r"(r3) : "r"(addr));
}

// ---- fast transcendentals ----
__device__ __forceinline__ float flog1p(float x) {       // x >= 0
    return (x < 1e-2f) ? x * (1.0f - 0.5f * x) : __logf(1.0f + x);
}
__device__ __forceinline__ float softplusf(float v) {
    return fmaxf(v, 0.0f) + flog1p(__expf(-fabsf(v)));
}

// K=32 panel via ldmatrix; 3 m-tiles (48-row warp tile)
template<int NTILES, int ASTRIDE>
__device__ __forceinline__ void panel_compute(uint32_t aLane, uint32_t wLane, float d[3][8][4])
{
    #pragma unroll
    for (int ks = 0; ks < 2; ks++) {
        const uint32_t aK = aLane + ks * 32;
        const uint32_t wK = wLane + ks * 32;
        uint32_t a[3][4];
        #pragma unroll
        for (int mt = 0; mt < 3; mt++)
            ldsm4(a[mt][0], a[mt][1], a[mt][2], a[mt][3], aK + mt * (16 * ASTRIDE * 2));
        #pragma unroll
        for (int ntp = 0; ntp < NTILES / 2; ntp++) {
            uint32_t b0, b1, b2, b3;
            ldsm4(b0, b1, b2, b3, wK + ntp * (16 * WST * 2));
            #pragma unroll
            for (int mt = 0; mt < 3; mt++) {
                mma16(d[mt][2 * ntp],     a[mt][0], a[mt][1], a[mt][2], a[mt][3], b0, b1);
                mma16(d[mt][2 * ntp + 1], a[mt][0], a[mt][1], a[mt][2], a[mt][3], b2, b3);
            }
        }
    }
}

// ---- prep kernels ----
__global__ void prep_w1(const float* __restrict__ W1) {
    int idx = blockIdx.x * blockDim.x + threadIdx.x;      // 81920
    int p = idx / 10240, rem = idx % 10240;
    int n = rem / 40, kk = rem % 40;
    float w = (kk < 32) ? W1[(p * 32 + kk) * 256 + n] : 0.0f;
    g_w1[idx] = __float2half_rn(w);
}
__global__ void prep_wo(const float* __restrict__ Wout) {
    int idx = blockIdx.x * blockDim.x + threadIdx.x;      // 61440
    int p = idx / 7680, rem = idx % 7680;
    int n = rem / 40, kk = rem % 40;
    float w = (kk < 32 && n < 184) ? Wout[(p * 32 + kk) * 184 + n] : 0.0f;
    g_wo[idx] = __float2half_rn(w);
}
__global__ void prep_w0(const float* __restrict__ W0) {
    int idx = blockIdx.x * blockDim.x + threadIdx.x;      // 10240
    int n = idx / 40, kk = idx % 40;
    __half v = __float2half_rn(0.0f);
    if (kk < 16) {
        float w = W0[(kk & 7) * 256 + n];
        v = __float2half_rn(w);
    } else if (kk < 24) {
        float w = W0[(kk - 16) * 256 + n];
        __half h = __float2half_rn(w);
        v = __float2half_rn(w - __half2float(h));
    }
    g_w0[idx] = v;
}

// ---- A0 staging: exact hi/lo split of x2 rows (tid<192, row clamped) ----
__device__ __forceinline__ void stage_a0(char* sm, const float* __restrict__ x,
                                         int row0, int tid, int B) {
    if (tid < RB) {
        const int rr = min(row0 + tid, B - 1);
        const float4* xp = (const float4*)(x + (size_t)rr * 16);
        float4 xc = xp[2], xd = xp[3];
        float xv[8] = {xc.x, xc.y, xc.z, xc.w, xd.x, xd.y, xd.z, xd.w};
        __half2* a0 = (__half2*)(sm + OFF_A0 + tid * 40 * 2);
        #pragma unroll
        for (int j = 0; j < 8; j += 2) {
            __half h0 = __float2half_rn(xv[j]);
            __half h1 = __float2half_rn(xv[j + 1]);
            __half l0 = __float2half_rn(xv[j] - __half2float(h0));
            __half l1 = __float2half_rn(xv[j + 1] - __half2float(h1));
            a0[j / 2]      = __half2(h0, h1);
            a0[4 + j / 2]  = __half2(l0, l1);
            a0[8 + j / 2]  = __half2(h0, h1);
            a0[12 + j / 2] = __half2(__float2half_rn(0.f), __float2half_rn(0.f));
            a0[16 + j / 2] = __half2(__float2half_rn(0.f), __float2half_rn(0.f));
        }
    }
}

// ---- main persistent kernel ----
__global__ void __launch_bounds__(NT, 1)
coupling_hmma_kernel(const float* __restrict__ x,
                     const float* __restrict__ b0,
                     const float* __restrict__ b1,
                     const float* __restrict__ bout,
                     float* __restrict__ out,
                     int B, int nTiles)
{
    extern __shared__ char sm[];
    const int tid = threadIdx.x;
    const int lane = tid & 31;
    const int wid = tid >> 5;
    const int mw = wid & 3, nw = wid >> 2;
    const int qr = lane >> 2, qc = (lane & 3) * 2;
    const uint32_t sm_u32 = smem_u32(sm);
    const uint32_t wp_u32 = sm_u32 + OFF_WP;

    float* b0s = (float*)(sm + OFF_B0S);
    float* b1s = (float*)(sm + OFF_B1S);
    float* bos = (float*)(sm + OFF_BOS);

    const int aRow = (lane & 15);
    const int aKof = (lane >> 4) * 8;
    const int wRow = (lane & 7) + ((lane >> 4) * 8);
    const int wKof = ((lane >> 3) & 1) * 8;
    const uint32_t aLaneA = sm_u32 + OFF_A + (((mw * 48 + aRow) * AST) + aKof) * 2;
    const uint32_t aLane0 = sm_u32 + OFF_A0 + (((mw * 48 + aRow) * 40) + aKof) * 2;
    const uint32_t wRel1 = (((nw * 64 + wRow) * WST) + wKof) * 2;
    const uint32_t wRel2 = (((nw * 48 + wRow) * WST) + wKof) * 2;
    const uint32_t wLane0 = sm_u32 + OFF_W0P + wRel1;

    // ---- one-time prologue: stage0 (slot0), W0P; consts; first A0 ----
    for (int i = tid; i < STG1_B / 16; i += NT)
        cp16(wp_u32 + i * 16, (const char*)g_w1 + i * 16);
    for (int i = tid; i < 1280; i += NT)
        cp16(sm_u32 + OFF_W0P + i * 16, (const char*)g_w0 + i * 16);
    CP_COMMIT();

    for (int i = tid; i < 256; i += NT) { b0s[i] = b0[i]; b1s[i] = b1[i]; }
    for (int i = tid; i < 192; i += NT) bos[i] = (i < 184) ? bout[i] : 0.0f;
    stage_a0(sm, x, blockIdx.x * RB, tid, B);
    __syncthreads();

    // ---- persistent tile loop ----
    for (int t = blockIdx.x; t < nTiles; t += GRID) {
        const int row0 = t * RB;
        const int rowsLeft = min(RB, B - row0);
        const bool more = (t + GRID < nTiles);

        float d[3][8][4];
        #pragma unroll
        for (int mt = 0; mt < 3; mt++)
            #pragma unroll
            for (int nt = 0; nt < 8; nt++)
                #pragma unroll
                for (int i = 0; i < 4; i++) d[mt][nt][i] = 0.0f;

        // ---- GEMM0 (A0 x resident W0P); covers in-flight stage0 load ----
        panel_compute<8, 40>(aLane0, wLane0, d);

        // ---- epilogue0: h0 = relu(d + b0) -> fp16 A tile ----
        #pragma unroll
        for (int mt = 0; mt < 3; mt++) {
            const int r0 = mw * 48 + mt * 16 + qr;
            #pragma unroll
            for (int nt = 0; nt < 8; nt++) {
                const int c = nw * 64 + nt * 8 + qc;
                const float g0 = b0s[c], g1 = b0s[c + 1];
                float v00 = fmaxf(d[mt][nt][0] + g0, 0.f);
                float v01 = fmaxf(d[mt][nt][1] + g1, 0.f);
                float v10 = fmaxf(d[mt][nt][2] + g0, 0.f);
                float v11 = fmaxf(d[mt][nt][3] + g1, 0.f);
                *(__half2*)(sm + OFF_A + ((size_t)r0 * AST + c) * 2) = __floats2half2_rn(v00, v01);
                *(__half2*)(sm + OFF_A + ((size_t)(r0 + 8) * AST + c) * 2) = __floats2half2_rn(v10, v11);
                #pragma unroll
                for (int i = 0; i < 4; i++) d[mt][nt][i] = 0.0f;
            }
        }

        // ---- x2 passthrough (hoisted off the tail; latency hides under stage0) ----
        if (tid < 384) {
            const int r = tid >> 1, q = tid & 1;
            if (r < rowsLeft) {
                const size_t gx = (size_t)(row0 + r) * 16 + 8 + q * 4;
                *(float4*)(out + gx) = *(const float4*)(x + gx);
            }
        }

        // ---- stage pipeline: s 0..3 = GEMM1, s 4..7 = GEMM2 (2 slots, wait-all) ----
        for (int s = 0; s < 8; s++) {
            CP_WAIT0();
            __syncthreads();

            if (s == 4) {
                // epilogue1: h1 = relu(d + b1) -> fp16 A tile
                #pragma unroll
                for (int mt = 0; mt < 3; mt++) {
                    const int r0 = mw * 48 + mt * 16 + qr;
                    #pragma unroll
                    for (int nt = 0; nt < 8; nt++) {
                        const int c = nw * 64 + nt * 8 + qc;
                        const float g0 = b1s[c], g1 = b1s[c + 1];
                        float v00 = fmaxf(d[mt][nt][0] + g0, 0.f);
                        float v01 = fmaxf(d[mt][nt][1] + g1, 0.f);
                        float v10 = fmaxf(d[mt][nt][2] + g0, 0.f);
                        float v11 = fmaxf(d[mt][nt][3] + g1, 0.f);
                        *(__half2*)(sm + OFF_A + ((size_t)r0 * AST + c) * 2) = __floats2half2_rn(v00, v01);
                        *(__half2*)(sm + OFF_A + ((size_t)(r0 + 8) * AST + c) * 2) = __floats2half2_rn(v10, v11);
                        #pragma unroll
                        for (int i = 0; i < 4; i++) d[mt][nt][i] = 0.0f;
                    }
                }
                __syncthreads();
            }

            if (s + 1 < 8) {
                const int ns = s + 1;
                uint32_t dst = wp_u32 + (ns & 1) * SLOT_B;
                if (ns < 4) {
                    const char* src = (const char*)g_w1 + (size_t)ns * STG1_B;
                    for (int i = tid; i < STG1_B / 16; i += NT) cp16(dst + i * 16, src + i * 16);
                } else {
                    const char* src = (const char*)g_wo + (size_t)(ns - 4) * STG2_B;
                    for (int i = tid; i < STG2_B / 16; i += NT) cp16(dst + i * 16, src + i * 16);
                }
            }
            CP_COMMIT();

            const uint32_t slot = wp_u32 + (s & 1) * SLOT_B;
            if (s < 4) {
                panel_compute<8, AST>(aLaneA + (2 * s) * 64,     slot + wRel1, d);
                panel_compute<8, AST>(aLaneA + (2 * s + 1) * 64, slot + PAN1_B + wRel1, d);
            } else {
                panel_compute<6, AST>(aLaneA + (2 * s - 8) * 64, slot + wRel2, d);
                panel_compute<6, AST>(aLaneA + (2 * s - 7) * 64, slot + PAN2_B + wRel2, d);
            }
        }
        __syncthreads();   // all GEMM2 A/W reads done

        // ---- epilogue2: raw = d + bout -> smem f32 [192][193] (overlaps A+slots) ----
        float* rawS = (float*)sm;
        #pragma unroll
        for (int mt = 0; mt < 3; mt++) {
            const int r0 = mw * 48 + mt * 16 + qr;
            #pragma unroll
            for (int nt = 0; nt < 6; nt++) {
                const int c = nw * 48 + nt * 8 + qc;
                rawS[r0 * RSTR + c]           = d[mt][nt][0] + bos[c];
                rawS[r0 * RSTR + c + 1]       = d[mt][nt][1] + bos[c + 1];
                rawS[(r0 + 8) * RSTR + c]     = d[mt][nt][2] + bos[c];
                rawS[(r0 + 8) * RSTR + c + 1] = d[mt][nt][3] + bos[c + 1];
            }
        }
        if (more) stage_a0(sm, x, (t + GRID) * RB, tid, B);   // A0 region free
        __syncthreads();   // rawS + next-A0 visible

        // ---- spline: 512 threads x 3 iters, 1 transform each ----
        {
            const float CNST = logf(expf(1.0f - 1e-4f) - 1.0f);
            #pragma unroll 1
            for (int k = 0; k < 3; k++) {
                const int g = k * NT + tid;           // 0..1535
                const int r = g >> 3, tt = g & 7;
                const int grow = row0 + r;
                const bool valid = (r < rowsLeft);
                const float xv = x[(size_t)min(grow, B - 1) * 16 + tt];
                const float* raw = rawS + r * RSTR + tt * 23;

                float rw[8], rh[8];
                #pragma unroll
                for (int c = 0; c < 8; c++) { rw[c] = raw[c]; rh[c] = raw[8 + c]; }

                float m = rw[0];
                #pragma unroll
                for (int c = 1; c < 8; c++) m = fmaxf(m, rw[c]);
                float sum = 0.0f, ew[8];
                #pragma unroll
                for (int c = 0; c < 8; c++) { ew[c] = __expf(rw[c] - m); sum += ew[c]; }
                float inv = __fdividef(1.0f, sum);
                float wdt[8];
                #pragma unroll
                for (int c = 0; c < 8; c++) wdt[c] = 2.0f * (1e-4f + (1.0f - 8e-4f) * ew[c] * inv);

                m = rh[0];
                #pragma unroll
                for (int c = 1; c < 8; c++) m = fmaxf(m, rh[c]);
                sum = 0.0f;
                #pragma unroll
                for (int c = 0; c < 8; c++) { ew[c] = __expf(rh[c] - m); sum += ew[c]; }
                inv = __fdividef(1.0f, sum);
                float hgt[8];
                #pragma unroll
                for (int c = 0; c < 8; c++) hgt[c] = 2.0f * (1e-4f + (1.0f - 8e-4f) * ew[c] * inv);

                float dv[9];
                dv[0] = 1.0f; dv[8] = 1.0f;
                #pragma unroll
                for (int c = 0; c < 7; c++) dv[c + 1] = softplusf(raw[16 + c] + CNST) + 1e-4f;

                const bool mask = (xv <= -0.999f) || (xv >= 0.999f);
                const float xin = mask ? 0.0f : xv;

                float cx = -1.0f, cy = -1.0f;
                float xk = -1.0f, yk = -1.0f, wk = wdt[0], hk = hgt[0], dk = dv[0], dk1 = dv[1];
                #pragma unroll
                for (int i = 0; i < 8; i++) {
                    if (cx <= xin) { xk = cx; yk = cy; wk = wdt[i]; hk = hgt[i]; dk = dv[i]; dk1 = dv[i + 1]; }
                    cx += wdt[i]; cy += hgt[i];
                }

                const float invwk = __fdividef(1.0f, wk);
                const float sk   = hk * invwk;
                const float eps  = (xin - xk) * invwk;
                const float et   = eps * (1.0f - eps);
                const float e2   = eps * eps;
                const float beta = sk + (dk1 + dk - 2.0f * sk) * et;
                const float alp  = hk * (sk * e2 + dk * et);
                const float y    = mask ? xv : (yk + __fdividef(alp, beta));
                const float ome  = 1.0f - eps;
                float ld = 2.0f * __logf(sk)
                         + __logf(dk1 * e2 + 2.0f * sk * et + dk * ome * ome)
                         - 2.0f * __logf(beta);
                ld = mask ? 0.0f : ld;

                if (valid)
                    out[(size_t)grow * 16 + tt] = y;

                // reduce logdet over the 8 lanes sharing this row
                ld += __shfl_xor_sync(0xffffffffu, ld, 1);
                ld += __shfl_xor_sync(0xffffffffu, ld, 2);
                ld += __shfl_xor_sync(0xffffffffu, ld, 4);
                if ((lane & 7) == 0 && valid)
                    out[(size_t)B * 16 + grow] = ld;
            }
        }
        __syncthreads();   // spline rawS reads done -> A + slots free

        // issue next tile's stage0 into slot0 (covered by next GEMM0+epi0)
        if (more) {
            for (int i = tid; i < STG1_B / 16; i += NT)
                cp16(wp_u32 + i * 16, (const char*)g_w1 + i * 16);
        }
        CP_COMMIT();
    }
}

extern "C" void kernel_launch(void* const* d_in, const int* in_sizes, int n_in,
                              void* d_out, int out_size) {
    const float* x    = (const float*)d_in[0];
    const float* W0   = (const float*)d_in[1];
    const float* b0   = (const float*)d_in[2];
    const float* W1   = (const float*)d_in[3];
    const float* b1   = (const float*)d_in[4];
    const float* Wout = (const float*)d_in[5];
    const float* bout = (const float*)d_in[6];
    float* out = (float*)d_out;

    const int B = in_sizes[0] / 16;
    const int nTiles = (B + RB - 1) / RB;

    prep_w1<<<320, 256>>>(W1);
    prep_wo<<<240, 256>>>(Wout);
    prep_w0<<<40, 256>>>(W0);

    cudaFuncSetAttribute(coupling_hmma_kernel,
                         cudaFuncAttributeMaxDynamicSharedMemorySize, SMEM_BYTES);
    coupling_hmma_kernel<<<GRID, NT, SMEM_BYTES>>>(x, b0, b1, bout, out, B, nTiles);
}